// round 6
// baseline (speedup 1.0000x reference)
#include <cuda_runtime.h>
#include <cstdint>
#include <math.h>

#define IMG   512
#define NANG  180
#define NBAT  4
#define CH    2          // angles per staged chunk (double-buffered)
#define NC    (NANG / CH)

// ---------------- scratch (no allocations allowed) ----------------
__device__ float  g_ff[IMG];                // frequency-domain filter
__device__ float  g_h[IMG];                 // spatial filter kernel (circular)
__device__ float2 g_trig[NANG];             // (sin, cos) per angle
__device__ float4 g_filt[NANG * IMG];       // filtered sinogram, batch-interleaved

__device__ __forceinline__ void cp_async16(unsigned int smem_addr, const void* gptr) {
    asm volatile("cp.async.ca.shared.global [%0], [%1], 16;\n"
                 :: "r"(smem_addr), "l"(gptr) : "memory");
}
__device__ __forceinline__ void cp_async_commit() {
    asm volatile("cp.async.commit_group;\n" ::: "memory");
}
template <int N>
__device__ __forceinline__ void cp_async_wait() {
    asm volatile("cp.async.wait_group %0;\n" :: "n"(N) : "memory");
}

// ---------------- setup stage 1: ff[k] = 2*Re(fft(f))[k] * sinc window ----------------
__global__ void setup_ff() {                // grid 16, block 32
    const int k = blockIdx.x * 32 + threadIdx.x;
    float a0 = 0.f, a1 = 0.f, a2 = 0.f, a3 = 0.f;   // 4-way ILP
    for (int j = 1; j < IMG; j += 8) {
        #pragma unroll
        for (int u = 0; u < 4; ++u) {
            int jj = j + 2 * u;
            int m = (jj <= 255) ? jj : (IMG - jj);
            float pm = (float)M_PI * (float)m;
            float fj = -1.0f / (pm * pm);
            int idx = (jj * k) & (IMG - 1);
            float c = cospif((float)idx * (1.0f / 256.0f));
            if (u == 0) a0 = fmaf(fj, c, a0);
            else if (u == 1) a1 = fmaf(fj, c, a1);
            else if (u == 2) a2 = fmaf(fj, c, a2);
            else a3 = fmaf(fj, c, a3);
        }
    }
    float ffk = 2.0f * (0.25f + ((a0 + a1) + (a2 + a3)));
    if (k > 0) {
        int m = (k <= 256) ? k : (IMG - k);          // |fftfreq|*N
        float x = (float)m * (1.0f / (float)IMG);    // exact
        ffk *= sinpif(x) / ((float)M_PI * x);        // sin(omega)/omega, even
    }
    g_ff[k] = ffk;
    if (k < NANG) {                                  // trig table (independent)
        double th = (double)k * (M_PI / 179.0);      // linspace(0,180,180) deg
        g_trig[k] = make_float2((float)sin(th), (float)cos(th));
    }
}

// ---------------- setup stage 2: h = ifft(ff) (cosine DFT) ----------------
__global__ void setup_h() {                 // grid 16, block 32
    const int q = blockIdx.x * 32 + threadIdx.x;
    float a0 = 0.f, a1 = 0.f, a2 = 0.f, a3 = 0.f;
    for (int k = 0; k < IMG; k += 4) {
        #pragma unroll
        for (int u = 0; u < 4; ++u) {
            int idx = ((k + u) * q) & (IMG - 1);
            float c = cospif((float)idx * (1.0f / 256.0f));
            float v = g_ff[k + u];
            if (u == 0) a0 = fmaf(v, c, a0);
            else if (u == 1) a1 = fmaf(v, c, a1);
            else if (u == 2) a2 = fmaf(v, c, a2);
            else a3 = fmaf(v, c, a3);
        }
    }
    g_h[q] = ((a0 + a1) + (a2 + a3)) * (1.0f / (float)IMG);
}

// ---------------- filtering: circular conv, reversed-kernel float4 sliding window ----------------
__global__ void filter_kernel(const float* __restrict__ sino) {
    __shared__ float s_row[2 * IMG];   // row duplicated -> no modulo
    __shared__ float s_hr[IMG];
    const int a = blockIdx.x;
    const int b = blockIdx.y;
    const int t = threadIdx.x;         // 0..127

    float4 r4 = reinterpret_cast<const float4*>(sino + (b * NANG + a) * IMG)[t];
    reinterpret_cast<float4*>(s_row)[t]       = r4;
    reinterpret_cast<float4*>(s_row)[t + 128] = r4;

    float4 h4 = reinterpret_cast<const float4*>(g_h)[t];   // h[4t..4t+3]
    s_hr[(IMG - (4 * t + 0)) & (IMG - 1)] = h4.x;
    s_hr[(IMG - (4 * t + 1)) & (IMG - 1)] = h4.y;
    s_hr[(IMG - (4 * t + 2)) & (IMG - 1)] = h4.z;
    s_hr[(IMG - (4 * t + 3)) & (IMG - 1)] = h4.w;
    __syncthreads();

    float acc0 = 0.f, acc1 = 0.f, acc2 = 0.f, acc3 = 0.f;
    const int base = 4 * t;
    float4 R0 = *reinterpret_cast<const float4*>(&s_row[base]);
    #pragma unroll 4
    for (int u = 0; u < IMG; u += 4) {
        float4 HR = *reinterpret_cast<const float4*>(&s_hr[u]);                 // broadcast
        float4 R1 = *reinterpret_cast<const float4*>(&s_row[base + u + 4]);     // sliding
        acc0 = fmaf(R0.x, HR.x, fmaf(R0.y, HR.y, fmaf(R0.z, HR.z, fmaf(R0.w, HR.w, acc0))));
        acc1 = fmaf(R0.y, HR.x, fmaf(R0.z, HR.y, fmaf(R0.w, HR.z, fmaf(R1.x, HR.w, acc1))));
        acc2 = fmaf(R0.z, HR.x, fmaf(R0.w, HR.y, fmaf(R1.x, HR.z, fmaf(R1.y, HR.w, acc2))));
        acc3 = fmaf(R0.w, HR.x, fmaf(R1.x, HR.y, fmaf(R1.y, HR.z, fmaf(R1.z, HR.w, acc3))));
        R0 = R1;
    }

    float* out = reinterpret_cast<float*>(g_filt);
    const int s = a * IMG + base;
    out[(s + 0) * 4 + b] = acc0;
    out[(s + 1) * 4 + b] = acc1;
    out[(s + 2) * 4 + b] = acc2;
    out[(s + 3) * 4 + b] = acc3;
}

// ---------------- backprojection: 32x16 tile / block, 2 px/thread, cp.async double buffer ----
// Padded row layout per staged row: slot 0 = zero, slots 1..512 = row[0..511], 513..515 = zero.
// p clamped to [-1, 513] before floor -> taps always in-bounds, boundary weights exact.
__global__ __launch_bounds__(256) void backproj_kernel(float* __restrict__ out) {
    __shared__ float4 s_rows[2][CH][IMG + 4];   // [buffer][rowInChunk][padded row]
    __shared__ float2 s_trig[NANG];

    const int t  = threadIdx.x;
    const int tx = t & 31;
    const int ty = t >> 5;             // 0..7
    const int w  = blockIdx.x * 32 + tx;
    const int y0 = blockIdx.y * 16 + ty;

    const float xf  = 255.0f - (float)w;
    const float yfa = (float)y0 - 256.0f;
    const float yfb = (float)(y0 + 8) - 256.0f;

    // block-level circle early-out (tile entirely outside radius 256)
    {
        float xhi = 255.0f - (float)(blockIdx.x * 32);
        float xlo = xhi - 31.0f;
        float ylo = (float)(blockIdx.y * 16) - 256.0f;
        float yhi = ylo + 15.0f;
        float mx = (xlo <= 0.0f && 0.0f <= xhi) ? 0.0f : fminf(fabsf(xlo), fabsf(xhi));
        float my = (ylo <= 0.0f && 0.0f <= yhi) ? 0.0f : fminf(fabsf(ylo), fabsf(yhi));
        if (fmaf(mx, mx, my * my) > 65536.0f) {
            #pragma unroll
            for (int k = 0; k < 2; ++k) {
                int pix = (y0 + 8 * k) * IMG + w;
                out[0 * IMG * IMG + pix] = 0.0f;
                out[1 * IMG * IMG + pix] = 0.0f;
                out[2 * IMG * IMG + pix] = 0.0f;
                out[3 * IMG * IMG + pix] = 0.0f;
            }
            return;
        }
    }

    if (t < NANG) s_trig[t] = g_trig[t];
    if (t < 2 * CH * 4) {              // zero the pad slots (both buffers) once
        int bc = t >> 2, s = t & 3;
        int slot = (s == 0) ? 0 : (IMG + s);   // 0, 513, 514, 515
        s_rows[bc >> 1][bc & 1][slot] = make_float4(0.f, 0.f, 0.f, 0.f);
    }

    const unsigned int sbase = (unsigned int)__cvta_generic_to_shared(&s_rows[0][0][0]);

    // stage chunk c into buffer buf: CH*512 float4 / 256 threads = CH*2 each
    auto stage = [&](int c, int buf) {
        #pragma unroll
        for (int i = 0; i < CH * 2; ++i) {
            int idx = i * 256 + t;                 // 0 .. CH*512-1
            int r   = idx >> 9;
            int p   = idx & (IMG - 1);
            unsigned int dst = sbase + (unsigned int)(((buf * CH + r) * (IMG + 4) + p + 1) * 16);
            cp_async16(dst, &g_filt[(c * CH + r) * IMG + p]);
        }
        cp_async_commit();
    };

    stage(0, 0);

    float ac0[4] = {0.f, 0.f, 0.f, 0.f};   // pixel a (y0)
    float ac1[4] = {0.f, 0.f, 0.f, 0.f};   // pixel b (y0+8)

    for (int c = 0; c < NC; ++c) {
        if (c + 1 < NC) stage(c + 1, (c + 1) & 1);
        if (c + 1 < NC) cp_async_wait<1>(); else cp_async_wait<0>();
        __syncthreads();

        #pragma unroll
        for (int ci = 0; ci < CH; ++ci) {
            const float2 sc   = s_trig[c * CH + ci];    // (sin, cos)
            const float  pxs  = fmaf(xf, sc.x, 256.0f);
            const float4* row = s_rows[c & 1][ci];

            // pixel a
            {
                float p  = fmaf(yfa, sc.y, pxs);
                p        = fminf(fmaxf(p, -1.0f), 513.0f);
                float fi = floorf(p);
                float fr = p - fi;
                float om = 1.0f - fr;
                int   i0 = (int)fi;
                const float4 v0 = row[i0 + 1];
                const float4 v1 = row[i0 + 2];
                ac0[0] = fmaf(om, v0.x, fmaf(fr, v1.x, ac0[0]));
                ac0[1] = fmaf(om, v0.y, fmaf(fr, v1.y, ac0[1]));
                ac0[2] = fmaf(om, v0.z, fmaf(fr, v1.z, ac0[2]));
                ac0[3] = fmaf(om, v0.w, fmaf(fr, v1.w, ac0[3]));
            }
            // pixel b
            {
                float p  = fmaf(yfb, sc.y, pxs);
                p        = fminf(fmaxf(p, -1.0f), 513.0f);
                float fi = floorf(p);
                float fr = p - fi;
                float om = 1.0f - fr;
                int   i0 = (int)fi;
                const float4 v0 = row[i0 + 1];
                const float4 v1 = row[i0 + 2];
                ac1[0] = fmaf(om, v0.x, fmaf(fr, v1.x, ac1[0]));
                ac1[1] = fmaf(om, v0.y, fmaf(fr, v1.y, ac1[1]));
                ac1[2] = fmaf(om, v0.z, fmaf(fr, v1.z, ac1[2]));
                ac1[3] = fmaf(om, v0.w, fmaf(fr, v1.w, ac1[3]));
            }
        }
        __syncthreads();
    }

    const float gscale = (float)(M_PI / (2.0 * NANG));
    {
        const bool inside = fmaf(xf, xf, yfa * yfa) <= 65536.0f;
        const float g = inside ? gscale : 0.0f;
        const int pix = y0 * IMG + w;
        out[0 * IMG * IMG + pix] = ac0[0] * g;
        out[1 * IMG * IMG + pix] = ac0[1] * g;
        out[2 * IMG * IMG + pix] = ac0[2] * g;
        out[3 * IMG * IMG + pix] = ac0[3] * g;
    }
    {
        const bool inside = fmaf(xf, xf, yfb * yfb) <= 65536.0f;
        const float g = inside ? gscale : 0.0f;
        const int pix = (y0 + 8) * IMG + w;
        out[0 * IMG * IMG + pix] = ac1[0] * g;
        out[1 * IMG * IMG + pix] = ac1[1] * g;
        out[2 * IMG * IMG + pix] = ac1[2] * g;
        out[3 * IMG * IMG + pix] = ac1[3] * g;
    }
}

// ---------------- launcher ----------------
extern "C" void kernel_launch(void* const* d_in, const int* in_sizes, int n_in,
                              void* d_out, int out_size) {
    const float* sino = (const float*)d_in[0];
    float* out = (float*)d_out;

    setup_ff<<<16, 32>>>();
    setup_h<<<16, 32>>>();
    filter_kernel<<<dim3(NANG, NBAT), 128>>>(sino);
    backproj_kernel<<<dim3(IMG / 32, IMG / 16), 256>>>(out);
}

// round 7
// speedup vs baseline: 1.3411x; 1.3411x over previous
#include <cuda_runtime.h>
#include <cuda_fp16.h>
#include <cstdint>
#include <math.h>

#define IMG   512
#define NANG  180
#define NBAT  4
#define CH    4          // angles per staged chunk (double-buffered)
#define NC    (NANG / CH)
#define RSLOT 520        // padded row slots (uint2 each): data at 2..513, pads 0,1,514..519

// ---------------- scratch (no allocations allowed) ----------------
__device__ float  g_ff[IMG];                // frequency-domain filter
__device__ float  g_h[IMG];                 // spatial filter kernel (circular)
__device__ float2 g_trig[NANG];             // (sin, cos) per angle
__device__ __half g_filth[NANG * IMG * 4];  // filtered sinogram, fp16, [angle][p][batch]

__device__ __forceinline__ void cp_async16(unsigned int smem_addr, const void* gptr) {
    asm volatile("cp.async.ca.shared.global [%0], [%1], 16;\n"
                 :: "r"(smem_addr), "l"(gptr) : "memory");
}
__device__ __forceinline__ void cp_async_commit() {
    asm volatile("cp.async.commit_group;\n" ::: "memory");
}
template <int N>
__device__ __forceinline__ void cp_async_wait() {
    asm volatile("cp.async.wait_group %0;\n" :: "n"(N) : "memory");
}

// ---------------- setup stage 1: ff[k] = 2*Re(fft(f))[k] * sinc window ----------------
__global__ void setup_ff() {                // grid 16, block 32
    const int k = blockIdx.x * 32 + threadIdx.x;
    float a0 = 0.f, a1 = 0.f, a2 = 0.f, a3 = 0.f;   // 4-way ILP
    for (int j = 1; j < IMG; j += 8) {
        #pragma unroll
        for (int u = 0; u < 4; ++u) {
            int jj = j + 2 * u;
            int m = (jj <= 255) ? jj : (IMG - jj);
            float pm = (float)M_PI * (float)m;
            float fj = -1.0f / (pm * pm);
            int idx = (jj * k) & (IMG - 1);
            float c = cospif((float)idx * (1.0f / 256.0f));
            if (u == 0) a0 = fmaf(fj, c, a0);
            else if (u == 1) a1 = fmaf(fj, c, a1);
            else if (u == 2) a2 = fmaf(fj, c, a2);
            else a3 = fmaf(fj, c, a3);
        }
    }
    float ffk = 2.0f * (0.25f + ((a0 + a1) + (a2 + a3)));
    if (k > 0) {
        int m = (k <= 256) ? k : (IMG - k);          // |fftfreq|*N
        float x = (float)m * (1.0f / (float)IMG);    // exact
        ffk *= sinpif(x) / ((float)M_PI * x);        // sin(omega)/omega, even
    }
    g_ff[k] = ffk;
    if (k < NANG) {                                  // trig table (independent)
        double th = (double)k * (M_PI / 179.0);      // linspace(0,180,180) deg
        g_trig[k] = make_float2((float)sin(th), (float)cos(th));
    }
}

// ---------------- setup stage 2: h = ifft(ff) (cosine DFT) ----------------
__global__ void setup_h() {                 // grid 16, block 32
    const int q = blockIdx.x * 32 + threadIdx.x;
    float a0 = 0.f, a1 = 0.f, a2 = 0.f, a3 = 0.f;
    for (int k = 0; k < IMG; k += 4) {
        #pragma unroll
        for (int u = 0; u < 4; ++u) {
            int idx = ((k + u) * q) & (IMG - 1);
            float c = cospif((float)idx * (1.0f / 256.0f));
            float v = g_ff[k + u];
            if (u == 0) a0 = fmaf(v, c, a0);
            else if (u == 1) a1 = fmaf(v, c, a1);
            else if (u == 2) a2 = fmaf(v, c, a2);
            else a3 = fmaf(v, c, a3);
        }
    }
    g_h[q] = ((a0 + a1) + (a2 + a3)) * (1.0f / (float)IMG);
}

// ---------------- filtering: circular conv, reversed-kernel float4 sliding window ----------------
__global__ void filter_kernel(const float* __restrict__ sino) {
    __shared__ float s_row[2 * IMG];   // row duplicated -> no modulo
    __shared__ float s_hr[IMG];
    const int a = blockIdx.x;
    const int b = blockIdx.y;
    const int t = threadIdx.x;         // 0..127

    float4 r4 = reinterpret_cast<const float4*>(sino + (b * NANG + a) * IMG)[t];
    reinterpret_cast<float4*>(s_row)[t]       = r4;
    reinterpret_cast<float4*>(s_row)[t + 128] = r4;

    float4 h4 = reinterpret_cast<const float4*>(g_h)[t];   // h[4t..4t+3]
    s_hr[(IMG - (4 * t + 0)) & (IMG - 1)] = h4.x;
    s_hr[(IMG - (4 * t + 1)) & (IMG - 1)] = h4.y;
    s_hr[(IMG - (4 * t + 2)) & (IMG - 1)] = h4.z;
    s_hr[(IMG - (4 * t + 3)) & (IMG - 1)] = h4.w;
    __syncthreads();

    float acc0 = 0.f, acc1 = 0.f, acc2 = 0.f, acc3 = 0.f;
    const int base = 4 * t;
    float4 R0 = *reinterpret_cast<const float4*>(&s_row[base]);
    #pragma unroll 4
    for (int u = 0; u < IMG; u += 4) {
        float4 HR = *reinterpret_cast<const float4*>(&s_hr[u]);                 // broadcast
        float4 R1 = *reinterpret_cast<const float4*>(&s_row[base + u + 4]);     // sliding
        acc0 = fmaf(R0.x, HR.x, fmaf(R0.y, HR.y, fmaf(R0.z, HR.z, fmaf(R0.w, HR.w, acc0))));
        acc1 = fmaf(R0.y, HR.x, fmaf(R0.z, HR.y, fmaf(R0.w, HR.z, fmaf(R1.x, HR.w, acc1))));
        acc2 = fmaf(R0.z, HR.x, fmaf(R0.w, HR.y, fmaf(R1.x, HR.z, fmaf(R1.y, HR.w, acc2))));
        acc3 = fmaf(R0.w, HR.x, fmaf(R1.x, HR.y, fmaf(R1.y, HR.z, fmaf(R1.z, HR.w, acc3))));
        R0 = R1;
    }

    // store fp16, layout [angle][p][batch]
    const int s = a * IMG + base;
    g_filth[(s + 0) * 4 + b] = __float2half_rn(acc0);
    g_filth[(s + 1) * 4 + b] = __float2half_rn(acc1);
    g_filth[(s + 2) * 4 + b] = __float2half_rn(acc2);
    g_filth[(s + 3) * 4 + b] = __float2half_rn(acc3);
}

// ---------------- backprojection: 32x32 tile / block, 4 px/thread, fp16 taps, cp.async ----
// Padded row layout (uint2 slots): slots 2..513 = row[0..511]; slots 0,1,514..519 = zero.
// p clamped to [-1, 513] before floor -> taps v0=slot[i0+2], v1=slot[i0+3] always in-bounds,
// boundary weights exact (clamped-out positions read zero pads).
__global__ __launch_bounds__(256) void backproj_kernel(float* __restrict__ out) {
    __shared__ uint2  s_rows[2][CH][RSLOT];   // [buffer][rowInChunk][padded row], 33.3 KB
    __shared__ float2 s_trig[NANG];

    const int t  = threadIdx.x;
    const int tx = t & 31;
    const int ty = t >> 5;             // 0..7
    const int w  = blockIdx.x * 32 + tx;
    const int y0 = blockIdx.y * 32 + ty;

    const float xf = 255.0f - (float)w;
    float yf[4];
    #pragma unroll
    for (int k = 0; k < 4; ++k) yf[k] = (float)(y0 + 8 * k) - 256.0f;

    // block-level circle early-out (tile entirely outside radius 256)
    {
        float xhi = 255.0f - (float)(blockIdx.x * 32);
        float xlo = xhi - 31.0f;
        float ylo = (float)(blockIdx.y * 32) - 256.0f;
        float yhi = ylo + 31.0f;
        float mx = (xlo <= 0.0f && 0.0f <= xhi) ? 0.0f : fminf(fabsf(xlo), fabsf(xhi));
        float my = (ylo <= 0.0f && 0.0f <= yhi) ? 0.0f : fminf(fabsf(ylo), fabsf(yhi));
        if (fmaf(mx, mx, my * my) > 65536.0f) {
            #pragma unroll
            for (int k = 0; k < 4; ++k) {
                int pix = (y0 + 8 * k) * IMG + w;
                out[0 * IMG * IMG + pix] = 0.0f;
                out[1 * IMG * IMG + pix] = 0.0f;
                out[2 * IMG * IMG + pix] = 0.0f;
                out[3 * IMG * IMG + pix] = 0.0f;
            }
            return;
        }
    }

    if (t < NANG) s_trig[t] = g_trig[t];
    if (t < 2 * CH * 8) {              // zero the 8 pad slots per row (both buffers)
        int rr = t >> 3, s = t & 7;    // rr: 0..7 over [buf][row]
        int slot = (s < 2) ? s : (512 + s);    // 0,1,514..519
        s_rows[rr >> 2][rr & 3][slot] = make_uint2(0u, 0u);
    }

    const unsigned int sbase = (unsigned int)__cvta_generic_to_shared(&s_rows[0][0][0]);

    // stage chunk c into buffer buf: CH rows * 4KB; 16B per thread per row
    auto stage = [&](int c, int buf) {
        #pragma unroll
        for (int r = 0; r < CH; ++r) {
            unsigned int dst = sbase + (unsigned int)((((buf * CH + r) * RSLOT) + 2 + 2 * t) * 8);
            const __half* src = &g_filth[((c * CH + r) * IMG + 2 * t) * 4];
            cp_async16(dst, src);
        }
        cp_async_commit();
    };

    stage(0, 0);

    float acc[4][4];
    #pragma unroll
    for (int k = 0; k < 4; ++k)
        #pragma unroll
        for (int b = 0; b < 4; ++b) acc[k][b] = 0.0f;

    for (int c = 0; c < NC; ++c) {
        if (c + 1 < NC) { stage(c + 1, (c + 1) & 1); cp_async_wait<1>(); }
        else            { cp_async_wait<0>(); }
        __syncthreads();

        #pragma unroll
        for (int ci = 0; ci < CH; ++ci) {
            const float2 sc  = s_trig[c * CH + ci];    // (sin, cos)
            const float  pxs = fmaf(xf, sc.x, 256.0f);
            const uint2* row = s_rows[c & 1][ci];

            #pragma unroll
            for (int k = 0; k < 4; ++k) {
                float p  = fmaf(yf[k], sc.y, pxs);
                p        = fminf(fmaxf(p, -1.0f), 513.0f);
                float fi = floorf(p);
                float fr = p - fi;
                float om = 1.0f - fr;
                int   i0 = (int)fi;

                uint2 u0 = row[i0 + 2];
                uint2 u1 = row[i0 + 3];
                float2 v0a = __half22float2(*reinterpret_cast<__half2*>(&u0.x));
                float2 v0b = __half22float2(*reinterpret_cast<__half2*>(&u0.y));
                float2 v1a = __half22float2(*reinterpret_cast<__half2*>(&u1.x));
                float2 v1b = __half22float2(*reinterpret_cast<__half2*>(&u1.y));

                acc[k][0] = fmaf(om, v0a.x, fmaf(fr, v1a.x, acc[k][0]));
                acc[k][1] = fmaf(om, v0a.y, fmaf(fr, v1a.y, acc[k][1]));
                acc[k][2] = fmaf(om, v0b.x, fmaf(fr, v1b.x, acc[k][2]));
                acc[k][3] = fmaf(om, v0b.y, fmaf(fr, v1b.y, acc[k][3]));
            }
        }
        __syncthreads();
    }

    const float gscale = (float)(M_PI / (2.0 * NANG));
    #pragma unroll
    for (int k = 0; k < 4; ++k) {
        const bool inside = fmaf(xf, xf, yf[k] * yf[k]) <= 65536.0f;
        const float g = inside ? gscale : 0.0f;
        const int pix = (y0 + 8 * k) * IMG + w;
        out[0 * IMG * IMG + pix] = acc[k][0] * g;
        out[1 * IMG * IMG + pix] = acc[k][1] * g;
        out[2 * IMG * IMG + pix] = acc[k][2] * g;
        out[3 * IMG * IMG + pix] = acc[k][3] * g;
    }
}

// ---------------- launcher ----------------
extern "C" void kernel_launch(void* const* d_in, const int* in_sizes, int n_in,
                              void* d_out, int out_size) {
    const float* sino = (const float*)d_in[0];
    float* out = (float*)d_out;

    setup_ff<<<16, 32>>>();
    setup_h<<<16, 32>>>();
    filter_kernel<<<dim3(NANG, NBAT), 128>>>(sino);
    backproj_kernel<<<dim3(IMG / 32, IMG / 32), 256>>>(out);
}

// round 9
// speedup vs baseline: 1.4757x; 1.1004x over previous
#include <cuda_runtime.h>
#include <cstdint>
#include <math.h>

#define IMG   512
#define NANG  180
#define NBAT  4
#define CH    4            // angles per staged chunk (double-buffered)
#define NC    (NANG / CH)
#define GROW  704          // padded global row (float2): 64 zeros | 512 data | 128 zeros
#define SROW  130          // smem slots per angle: 2 guard zeros + 64 (b01) + 64 (b23)

// ---------------- scratch (no allocations allowed) ----------------
__device__ float  g_ff[IMG];                              // frequency-domain filter
__device__ float  g_h[IMG];                               // spatial filter kernel
__device__ float2 g_trig[NANG];                           // (sin, cos) per angle
__device__ __align__(16) float2 g_filt2[NANG][2][GROW];   // filtered rows, fp32 batch-pairs, padded

__device__ __forceinline__ void cp_async16(unsigned int smem_addr, const void* gptr) {
    asm volatile("cp.async.ca.shared.global [%0], [%1], 16;\n"
                 :: "r"(smem_addr), "l"(gptr) : "memory");
}
__device__ __forceinline__ void cp_async_commit() {
    asm volatile("cp.async.commit_group;\n" ::: "memory");
}
template <int N>
__device__ __forceinline__ void cp_async_wait() {
    asm volatile("cp.async.wait_group %0;\n" :: "n"(N) : "memory");
}

// ---------------- setup stage 1: ff[k] = 2*Re(fft(f))[k] * sinc window ----------------
__global__ void setup_ff() {                // grid 16, block 32
    __shared__ float s_fj[256];             // f[2i+1] table, computed cooperatively
    const int t = threadIdx.x;
    const int k = blockIdx.x * 32 + t;
    #pragma unroll
    for (int i = 0; i < 8; ++i) {
        int jidx = t * 8 + i;               // j = 2*jidx+1
        int jj = 2 * jidx + 1;
        int m = (jj <= 255) ? jj : (IMG - jj);
        float pm = (float)M_PI * (float)m;
        s_fj[jidx] = -1.0f / (pm * pm);
    }
    __syncthreads();

    float a0 = 0.f, a1 = 0.f, a2 = 0.f, a3 = 0.f;   // 4-way ILP
    for (int ji = 0; ji < 256; ji += 4) {
        #pragma unroll
        for (int u = 0; u < 4; ++u) {
            int jj = 2 * (ji + u) + 1;
            int idx = (jj * k) & (IMG - 1);
            float c = cospif((float)idx * (1.0f / 256.0f));
            float fj = s_fj[ji + u];
            if (u == 0) a0 = fmaf(fj, c, a0);
            else if (u == 1) a1 = fmaf(fj, c, a1);
            else if (u == 2) a2 = fmaf(fj, c, a2);
            else a3 = fmaf(fj, c, a3);
        }
    }
    float ffk = 2.0f * (0.25f + ((a0 + a1) + (a2 + a3)));
    if (k > 0) {
        int m = (k <= 256) ? k : (IMG - k);          // |fftfreq|*N
        float x = (float)m * (1.0f / (float)IMG);    // exact
        ffk *= sinpif(x) / ((float)M_PI * x);        // sin(omega)/omega, even
    }
    g_ff[k] = ffk;
    if (k < NANG) {
        double th = (double)k * (M_PI / 179.0);      // linspace(0,180,180) deg
        g_trig[k] = make_float2((float)sin(th), (float)cos(th));
    }
}

// ---------------- setup stage 2: h = ifft(ff) (cosine DFT), ff cached in smem ----------------
__global__ void setup_h() {                 // grid 16, block 32
    __shared__ float s_ff[IMG];
    const int t = threadIdx.x;
    const int q = blockIdx.x * 32 + t;
    #pragma unroll
    for (int i = 0; i < 4; ++i)
        reinterpret_cast<float4*>(s_ff)[i * 32 + t] = reinterpret_cast<const float4*>(g_ff)[i * 32 + t];
    __syncthreads();

    float a0 = 0.f, a1 = 0.f, a2 = 0.f, a3 = 0.f;
    for (int k = 0; k < IMG; k += 4) {
        #pragma unroll
        for (int u = 0; u < 4; ++u) {
            int idx = ((k + u) * q) & (IMG - 1);
            float c = cospif((float)idx * (1.0f / 256.0f));
            float v = s_ff[k + u];
            if (u == 0) a0 = fmaf(v, c, a0);
            else if (u == 1) a1 = fmaf(v, c, a1);
            else if (u == 2) a2 = fmaf(v, c, a2);
            else a3 = fmaf(v, c, a3);
        }
    }
    g_h[q] = ((a0 + a1) + (a2 + a3)) * (1.0f / (float)IMG);
}

// ---------------- filtering: circular conv + write padded fp32 batch-pair rows ----------------
__global__ void filter_kernel(const float* __restrict__ sino) {
    __shared__ float s_row[2 * IMG];   // row duplicated -> no modulo
    __shared__ float s_hr[IMG];
    const int a = blockIdx.x;
    const int b = blockIdx.y;
    const int t = threadIdx.x;         // 0..127

    float4 r4 = reinterpret_cast<const float4*>(sino + (b * NANG + a) * IMG)[t];
    reinterpret_cast<float4*>(s_row)[t]       = r4;
    reinterpret_cast<float4*>(s_row)[t + 128] = r4;

    float4 h4 = reinterpret_cast<const float4*>(g_h)[t];   // h[4t..4t+3]
    s_hr[(IMG - (4 * t + 0)) & (IMG - 1)] = h4.x;
    s_hr[(IMG - (4 * t + 1)) & (IMG - 1)] = h4.y;
    s_hr[(IMG - (4 * t + 2)) & (IMG - 1)] = h4.z;
    s_hr[(IMG - (4 * t + 3)) & (IMG - 1)] = h4.w;

    // zero the global pads for this angle (blocks b=0,1 handle regions 0,1)
    if (b < 2) {
        float2* reg = &g_filt2[a][b][0];
        #pragma unroll
        for (int i = 0; i < 2; ++i) {
            int idx = i * 128 + t;                  // 0..255, need 0..191
            if (idx < 192) {
                int slot = (idx < 64) ? idx : (idx + 512);   // [0,64) and [576,704)
                reg[slot] = make_float2(0.f, 0.f);
            }
        }
    }
    __syncthreads();

    float acc0 = 0.f, acc1 = 0.f, acc2 = 0.f, acc3 = 0.f;
    const int base = 4 * t;
    float4 R0 = *reinterpret_cast<const float4*>(&s_row[base]);
    #pragma unroll 4
    for (int u = 0; u < IMG; u += 4) {
        float4 HR = *reinterpret_cast<const float4*>(&s_hr[u]);                 // broadcast
        float4 R1 = *reinterpret_cast<const float4*>(&s_row[base + u + 4]);     // sliding
        acc0 = fmaf(R0.x, HR.x, fmaf(R0.y, HR.y, fmaf(R0.z, HR.z, fmaf(R0.w, HR.w, acc0))));
        acc1 = fmaf(R0.y, HR.x, fmaf(R0.z, HR.y, fmaf(R0.w, HR.z, fmaf(R1.x, HR.w, acc1))));
        acc2 = fmaf(R0.z, HR.x, fmaf(R0.w, HR.y, fmaf(R1.x, HR.z, fmaf(R1.y, HR.w, acc2))));
        acc3 = fmaf(R0.w, HR.x, fmaf(R1.x, HR.y, fmaf(R1.y, HR.z, fmaf(R1.z, HR.w, acc3))));
        R0 = R1;
    }

    // store fp32 into padded batch-pair layout: region b>>1, component b&1
    float* dstf = reinterpret_cast<float*>(&g_filt2[a][b >> 1][0]);
    const int comp = b & 1;
    dstf[(64 + base + 0) * 2 + comp] = acc0;
    dstf[(64 + base + 1) * 2 + comp] = acc1;
    dstf[(64 + base + 2) * 2 + comp] = acc2;
    dstf[(64 + base + 3) * 2 + comp] = acc3;
}

// ---------------- backprojection: 32x16 tile / block, 2 px/thread, windowed fp32 staging ----
// Per (block, angle): stage a 64-sample window starting at base = floor(p_min_tile) & ~1.
// Tile projection span <= 31*(sin+|cos|) + 1 < 46, so window always covers both taps.
// Smem angle layout: [2 guard zeros][64 b01][64 b23]; local index il = floor(p) - base >= -1
// only via fp epsilon, landing on guard slot with ~0 weight.
__global__ __launch_bounds__(256) void backproj_kernel(float* __restrict__ out) {
    __shared__ float2 s_rows[2 * CH * SROW];    // 8.3 KB, double-buffered chunks
    __shared__ float2 s_trig[NANG];

    const int t  = threadIdx.x;
    const int tx = t & 31;
    const int ty = t >> 5;             // 0..7
    const int w  = blockIdx.x * 32 + tx;
    const int y0 = blockIdx.y * 16 + ty;

    const float xf  = 255.0f - (float)w;
    const float yfa = (float)y0 - 256.0f;
    const float yfb = (float)(y0 + 8) - 256.0f;

    // block-level circle early-out (tile entirely outside radius 256)
    {
        float xhi = 255.0f - (float)(blockIdx.x * 32);
        float xlo = xhi - 31.0f;
        float ylo = (float)(blockIdx.y * 16) - 256.0f;
        float yhi = ylo + 15.0f;
        float mx = (xlo <= 0.0f && 0.0f <= xhi) ? 0.0f : fminf(fabsf(xlo), fabsf(xhi));
        float my = (ylo <= 0.0f && 0.0f <= yhi) ? 0.0f : fminf(fabsf(ylo), fabsf(yhi));
        if (fmaf(mx, mx, my * my) > 65536.0f) {
            #pragma unroll
            for (int k = 0; k < 2; ++k) {
                int pix = (y0 + 8 * k) * IMG + w;
                out[0 * IMG * IMG + pix] = 0.0f;
                out[1 * IMG * IMG + pix] = 0.0f;
                out[2 * IMG * IMG + pix] = 0.0f;
                out[3 * IMG * IMG + pix] = 0.0f;
            }
            return;
        }
    }

    if (t < NANG) s_trig[t] = g_trig[t];
    if (t < 2 * CH * 2) {              // zero guard slots [0],[1] of each [buf][ang]
        int ba = t >> 1;
        s_rows[ba * SROW + (t & 1)] = make_float2(0.f, 0.f);
    }
    __syncthreads();                   // trig + guards visible before base calc / staging

    const float xfmin = 224.0f - 32.0f * (float)blockIdx.x;
    const float yfmin = 16.0f * (float)blockIdx.y - 256.0f;
    const float yfmax = yfmin + 15.0f;

    const unsigned int sbase = (unsigned int)__cvta_generic_to_shared(s_rows);

    // per-thread staging: thread handles angle (t>>6), region ((t>>5)&1), 16B chunk (t&31)
    const int st_ang = t >> 6;
    const int st_r   = (t >> 5) & 1;
    const int st_j   = t & 31;

    auto stage = [&](int c, int buf) {
        float2 sc = s_trig[c * CH + st_ang];
        float pm  = 256.0f + xfmin * sc.x + fminf(yfmin * sc.y, yfmax * sc.y);
        int base  = ((int)floorf(pm)) & ~1;
        const char* src = (const char*)&g_filt2[c * CH + st_ang][st_r][64 + base] + st_j * 16;
        unsigned int dst = sbase +
            (unsigned int)(((buf * CH + st_ang) * SROW + 2 + st_r * 64) * 8 + st_j * 16);
        cp_async16(dst, src);
        cp_async_commit();
    };

    stage(0, 0);

    float ac0[4] = {0.f, 0.f, 0.f, 0.f};   // pixel a (y0)
    float ac1[4] = {0.f, 0.f, 0.f, 0.f};   // pixel b (y0+8)

    for (int c = 0; c < NC; ++c) {
        if (c + 1 < NC) { stage(c + 1, (c + 1) & 1); cp_async_wait<1>(); }
        else            { cp_async_wait<0>(); }
        __syncthreads();

        #pragma unroll
        for (int ci = 0; ci < CH; ++ci) {
            float2 sc = s_trig[c * CH + ci];
            float pm  = 256.0f + xfmin * sc.x + fminf(yfmin * sc.y, yfmax * sc.y);
            int base  = ((int)floorf(pm)) & ~1;          // matches stage exactly
            float o   = 256.0f - (float)base;
            float pq  = fmaf(xf, sc.x, o);
            const float2* ang = &s_rows[((c & 1) * CH + ci) * SROW];

            // pixel a
            {
                float q  = fmaf(yfa, sc.y, pq);
                float fl = floorf(q);
                float fr = q - fl;
                float om = 1.0f - fr;
                int   il = (int)fl;
                float2 vA0 = ang[2 + il];
                float2 vA1 = ang[3 + il];
                float2 vB0 = ang[66 + il];
                float2 vB1 = ang[67 + il];
                ac0[0] = fmaf(om, vA0.x, fmaf(fr, vA1.x, ac0[0]));
                ac0[1] = fmaf(om, vA0.y, fmaf(fr, vA1.y, ac0[1]));
                ac0[2] = fmaf(om, vB0.x, fmaf(fr, vB1.x, ac0[2]));
                ac0[3] = fmaf(om, vB0.y, fmaf(fr, vB1.y, ac0[3]));
            }
            // pixel b
            {
                float q  = fmaf(yfb, sc.y, pq);
                float fl = floorf(q);
                float fr = q - fl;
                float om = 1.0f - fr;
                int   il = (int)fl;
                float2 vA0 = ang[2 + il];
                float2 vA1 = ang[3 + il];
                float2 vB0 = ang[66 + il];
                float2 vB1 = ang[67 + il];
                ac1[0] = fmaf(om, vA0.x, fmaf(fr, vA1.x, ac1[0]));
                ac1[1] = fmaf(om, vA0.y, fmaf(fr, vA1.y, ac1[1]));
                ac1[2] = fmaf(om, vB0.x, fmaf(fr, vB1.x, ac1[2]));
                ac1[3] = fmaf(om, vB0.y, fmaf(fr, vB1.y, ac1[3]));
            }
        }
        __syncthreads();
    }

    const float gscale = (float)(M_PI / (2.0 * NANG));
    {
        const bool inside = fmaf(xf, xf, yfa * yfa) <= 65536.0f;
        const float g = inside ? gscale : 0.0f;
        const int pix = y0 * IMG + w;
        out[0 * IMG * IMG + pix] = ac0[0] * g;
        out[1 * IMG * IMG + pix] = ac0[1] * g;
        out[2 * IMG * IMG + pix] = ac0[2] * g;
        out[3 * IMG * IMG + pix] = ac0[3] * g;
    }
    {
        const bool inside = fmaf(xf, xf, yfb * yfb) <= 65536.0f;
        const float g = inside ? gscale : 0.0f;
        const int pix = (y0 + 8) * IMG + w;
        out[0 * IMG * IMG + pix] = ac1[0] * g;
        out[1 * IMG * IMG + pix] = ac1[1] * g;
        out[2 * IMG * IMG + pix] = ac1[2] * g;
        out[3 * IMG * IMG + pix] = ac1[3] * g;
    }
}

// ---------------- launcher ----------------
extern "C" void kernel_launch(void* const* d_in, const int* in_sizes, int n_in,
                              void* d_out, int out_size) {
    const float* sino = (const float*)d_in[0];
    float* out = (float*)d_out;

    setup_ff<<<16, 32>>>();
    setup_h<<<16, 32>>>();
    filter_kernel<<<dim3(NANG, NBAT), 128>>>(sino);
    backproj_kernel<<<dim3(IMG / 32, IMG / 16), 256>>>(out);
}

// round 11
// speedup vs baseline: 1.5406x; 1.0439x over previous
#include <cuda_runtime.h>
#include <cstdint>
#include <math.h>

#define IMG   512
#define NANG  180
#define NBAT  4
#define CH    4            // angles per staged chunk (double-buffered)
#define NC    (NANG / CH)
#define GROW  704          // padded global row (float4): 64 zeros | 512 data | 128 zeros

// ---------------- scratch (no allocations allowed) ----------------
__device__ float  g_ff[IMG];                          // frequency-domain filter
__device__ float  g_h[IMG];                           // spatial filter kernel
__device__ float2 g_trig[NANG];                       // (sin, cos) per angle
__device__ __align__(16) float4 g_filt4[NANG][GROW];  // filtered rows, batch-quads, padded

__device__ __forceinline__ void cp_async16(unsigned int smem_addr, const void* gptr) {
    asm volatile("cp.async.ca.shared.global [%0], [%1], 16;\n"
                 :: "r"(smem_addr), "l"(gptr) : "memory");
}
__device__ __forceinline__ void cp_async_commit() {
    asm volatile("cp.async.commit_group;\n" ::: "memory");
}
template <int N>
__device__ __forceinline__ void cp_async_wait() {
    asm volatile("cp.async.wait_group %0;\n" :: "n"(N) : "memory");
}

// ---------------- setup stage 1: ff[k] = 2*Re(fft(f))[k] * sinc window ----------------
__global__ void setup_ff() {                // grid 16, block 32
    __shared__ float s_fj[256];             // f[2i+1] table, computed cooperatively
    const int t = threadIdx.x;
    const int k = blockIdx.x * 32 + t;
    #pragma unroll
    for (int i = 0; i < 8; ++i) {
        int jidx = t * 8 + i;               // j = 2*jidx+1
        int jj = 2 * jidx + 1;
        int m = (jj <= 255) ? jj : (IMG - jj);
        float pm = (float)M_PI * (float)m;
        s_fj[jidx] = -1.0f / (pm * pm);
    }
    __syncthreads();

    float a0 = 0.f, a1 = 0.f, a2 = 0.f, a3 = 0.f;   // 4-way ILP
    for (int ji = 0; ji < 256; ji += 4) {
        #pragma unroll
        for (int u = 0; u < 4; ++u) {
            int jj = 2 * (ji + u) + 1;
            int idx = (jj * k) & (IMG - 1);
            float c = cospif((float)idx * (1.0f / 256.0f));
            float fj = s_fj[ji + u];
            if (u == 0) a0 = fmaf(fj, c, a0);
            else if (u == 1) a1 = fmaf(fj, c, a1);
            else if (u == 2) a2 = fmaf(fj, c, a2);
            else a3 = fmaf(fj, c, a3);
        }
    }
    float ffk = 2.0f * (0.25f + ((a0 + a1) + (a2 + a3)));
    if (k > 0) {
        int m = (k <= 256) ? k : (IMG - k);          // |fftfreq|*N
        float x = (float)m * (1.0f / (float)IMG);    // exact
        ffk *= sinpif(x) / ((float)M_PI * x);        // sin(omega)/omega, even
    }
    g_ff[k] = ffk;
    if (k < NANG) {
        double th = (double)k * (M_PI / 179.0);      // linspace(0,180,180) deg
        g_trig[k] = make_float2((float)sin(th), (float)cos(th));
    }
}

// ---------------- setup stage 2: h = ifft(ff) (cosine DFT), ff cached in smem ----------------
__global__ void setup_h() {                 // grid 16, block 32
    __shared__ float s_ff[IMG];
    const int t = threadIdx.x;
    const int q = blockIdx.x * 32 + t;
    #pragma unroll
    for (int i = 0; i < 4; ++i)
        reinterpret_cast<float4*>(s_ff)[i * 32 + t] = reinterpret_cast<const float4*>(g_ff)[i * 32 + t];
    __syncthreads();

    float a0 = 0.f, a1 = 0.f, a2 = 0.f, a3 = 0.f;
    for (int k = 0; k < IMG; k += 4) {
        #pragma unroll
        for (int u = 0; u < 4; ++u) {
            int idx = ((k + u) * q) & (IMG - 1);
            float c = cospif((float)idx * (1.0f / 256.0f));
            float v = s_ff[k + u];
            if (u == 0) a0 = fmaf(v, c, a0);
            else if (u == 1) a1 = fmaf(v, c, a1);
            else if (u == 2) a2 = fmaf(v, c, a2);
            else a3 = fmaf(v, c, a3);
        }
    }
    g_h[q] = ((a0 + a1) + (a2 + a3)) * (1.0f / (float)IMG);
}

// ---------------- filtering: circular conv + write padded batch-quad rows ----------------
__global__ void filter_kernel(const float* __restrict__ sino) {
    __shared__ float s_row[2 * IMG];   // row duplicated -> no modulo
    __shared__ float s_hr[IMG];
    const int a = blockIdx.x;
    const int b = blockIdx.y;
    const int t = threadIdx.x;         // 0..127

    float4 r4 = reinterpret_cast<const float4*>(sino + (b * NANG + a) * IMG)[t];
    reinterpret_cast<float4*>(s_row)[t]       = r4;
    reinterpret_cast<float4*>(s_row)[t + 128] = r4;

    float4 h4 = reinterpret_cast<const float4*>(g_h)[t];   // h[4t..4t+3]
    s_hr[(IMG - (4 * t + 0)) & (IMG - 1)] = h4.x;
    s_hr[(IMG - (4 * t + 1)) & (IMG - 1)] = h4.y;
    s_hr[(IMG - (4 * t + 2)) & (IMG - 1)] = h4.z;
    s_hr[(IMG - (4 * t + 3)) & (IMG - 1)] = h4.w;

    // zero the global pads for this angle
    if (b == 0) {
        if (t < 64) g_filt4[a][t] = make_float4(0.f, 0.f, 0.f, 0.f);
    } else if (b == 1) {
        g_filt4[a][576 + t] = make_float4(0.f, 0.f, 0.f, 0.f);   // 576..703
    }
    __syncthreads();

    float acc0 = 0.f, acc1 = 0.f, acc2 = 0.f, acc3 = 0.f;
    const int obase = 4 * t;
    float4 R0 = *reinterpret_cast<const float4*>(&s_row[obase]);
    #pragma unroll 4
    for (int u = 0; u < IMG; u += 4) {
        float4 HR = *reinterpret_cast<const float4*>(&s_hr[u]);                   // broadcast
        float4 R1 = *reinterpret_cast<const float4*>(&s_row[obase + u + 4]);      // sliding
        acc0 = fmaf(R0.x, HR.x, fmaf(R0.y, HR.y, fmaf(R0.z, HR.z, fmaf(R0.w, HR.w, acc0))));
        acc1 = fmaf(R0.y, HR.x, fmaf(R0.z, HR.y, fmaf(R0.w, HR.z, fmaf(R1.x, HR.w, acc1))));
        acc2 = fmaf(R0.z, HR.x, fmaf(R0.w, HR.y, fmaf(R1.x, HR.z, fmaf(R1.y, HR.w, acc2))));
        acc3 = fmaf(R0.w, HR.x, fmaf(R1.x, HR.y, fmaf(R1.y, HR.z, fmaf(R1.z, HR.w, acc3))));
        R0 = R1;
    }

    // scatter into batch-quad layout: g_filt4[a][64+p].{component b}
    float* dstf = reinterpret_cast<float*>(&g_filt4[a][64]);
    dstf[(obase + 0) * 4 + b] = acc0;
    dstf[(obase + 1) * 4 + b] = acc1;
    dstf[(obase + 2) * 4 + b] = acc2;
    dstf[(obase + 3) * 4 + b] = acc3;
}

// ---------------- backprojection: 32x32 tile / block, 4 px/thread, float4 windows ----------
// Per (block, angle): stage 64 float4 samples starting at base-2, base = floor(p_min_tile).
// Surviving tiles intersect the circle -> base >= -44; span < 45 -> window covers both taps;
// zeros come from the global pads. Metadata (sin, cos, 258-base) published via smem float4.
__global__ __launch_bounds__(256) void backproj_kernel(float* __restrict__ out) {
    __shared__ float4 s_win[2][CH][64];     // 8 KB, double-buffered windows
    __shared__ float4 s_meta[2][CH];        // (sin, cos, offset, -)
    __shared__ float2 s_trig[NANG];

    const int t  = threadIdx.x;
    const int tx = t & 31;
    const int ty = t >> 5;             // 0..7
    const int w  = blockIdx.x * 32 + tx;
    const int y0 = blockIdx.y * 32 + ty;

    const float xf = 255.0f - (float)w;
    float yf[4];
    #pragma unroll
    for (int k = 0; k < 4; ++k) yf[k] = (float)(y0 + 8 * k) - 256.0f;

    // block-level circle early-out (tile entirely outside radius 256)
    {
        float xhi = 255.0f - (float)(blockIdx.x * 32);
        float xlo = xhi - 31.0f;
        float ylo = (float)(blockIdx.y * 32) - 256.0f;
        float yhi = ylo + 31.0f;
        float mx = (xlo <= 0.0f && 0.0f <= xhi) ? 0.0f : fminf(fabsf(xlo), fabsf(xhi));
        float my = (ylo <= 0.0f && 0.0f <= yhi) ? 0.0f : fminf(fabsf(ylo), fabsf(yhi));
        if (fmaf(mx, mx, my * my) > 65536.0f) {
            #pragma unroll
            for (int k = 0; k < 4; ++k) {
                int pix = (y0 + 8 * k) * IMG + w;
                out[0 * IMG * IMG + pix] = 0.0f;
                out[1 * IMG * IMG + pix] = 0.0f;
                out[2 * IMG * IMG + pix] = 0.0f;
                out[3 * IMG * IMG + pix] = 0.0f;
            }
            return;
        }
    }

    if (t < NANG) s_trig[t] = g_trig[t];
    __syncthreads();                   // trig visible before staging

    const float xfmin = 224.0f - 32.0f * (float)blockIdx.x;
    const float yfmin = 32.0f * (float)blockIdx.y - 256.0f;
    const float yfmax = yfmin + 31.0f;

    const unsigned int sbase = (unsigned int)__cvta_generic_to_shared(&s_win[0][0][0]);

    const int st_ang = t >> 6;         // 0..3
    const int st_j   = t & 63;         // 0..63

    auto stage = [&](int c, int buf) {
        float2 sc = s_trig[c * CH + st_ang];
        float t0  = fmaf(xfmin, sc.x, 256.0f);
        float pmw = fminf(fmaf(yfmin, sc.y, t0), fmaf(yfmax, sc.y, t0));
        int base  = (int)floorf(pmw);
        const float4* src = &g_filt4[c * CH + st_ang][64 + base - 2 + st_j];
        unsigned int dst = sbase + (unsigned int)(((buf * CH + st_ang) * 64 + st_j) * 16);
        cp_async16(dst, src);
        if (st_j == 0)
            s_meta[buf][st_ang] = make_float4(sc.x, sc.y, 258.0f - (float)base, 0.f);
        cp_async_commit();
    };

    stage(0, 0);

    float acc[4][4];
    #pragma unroll
    for (int k = 0; k < 4; ++k)
        #pragma unroll
        for (int b = 0; b < 4; ++b) acc[k][b] = 0.0f;

    for (int c = 0; c < NC; ++c) {
        if (c + 1 < NC) { stage(c + 1, (c + 1) & 1); cp_async_wait<1>(); }
        else            { cp_async_wait<0>(); }
        __syncthreads();

        #pragma unroll
        for (int ci = 0; ci < CH; ++ci) {
            const float4 m  = s_meta[c & 1][ci];        // sin, cos, offset
            const float  pq = fmaf(xf, m.x, m.z);
            const float4* win = s_win[c & 1][ci];

            #pragma unroll
            for (int k = 0; k < 4; ++k) {
                float q  = fmaf(yf[k], m.y, pq);
                float fl = floorf(q);
                float fr = q - fl;
                float om = 1.0f - fr;
                int   il = (int)fl;

                float4 v0 = win[il];
                float4 v1 = win[il + 1];

                acc[k][0] = fmaf(om, v0.x, fmaf(fr, v1.x, acc[k][0]));
                acc[k][1] = fmaf(om, v0.y, fmaf(fr, v1.y, acc[k][1]));
                acc[k][2] = fmaf(om, v0.z, fmaf(fr, v1.z, acc[k][2]));
                acc[k][3] = fmaf(om, v0.w, fmaf(fr, v1.w, acc[k][3]));
            }
        }
        __syncthreads();               // protect windows/meta before next overwrite
    }

    const float gscale = (float)(M_PI / (2.0 * NANG));
    #pragma unroll
    for (int k = 0; k < 4; ++k) {
        const bool inside = fmaf(xf, xf, yf[k] * yf[k]) <= 65536.0f;
        const float g = inside ? gscale : 0.0f;
        const int pix = (y0 + 8 * k) * IMG + w;
        out[0 * IMG * IMG + pix] = acc[k][0] * g;
        out[1 * IMG * IMG + pix] = acc[k][1] * g;
        out[2 * IMG * IMG + pix] = acc[k][2] * g;
        out[3 * IMG * IMG + pix] = acc[k][3] * g;
    }
}

// ---------------- launcher ----------------
extern "C" void kernel_launch(void* const* d_in, const int* in_sizes, int n_in,
                              void* d_out, int out_size) {
    const float* sino = (const float*)d_in[0];
    float* out = (float*)d_out;

    setup_ff<<<16, 32>>>();
    setup_h<<<16, 32>>>();
    filter_kernel<<<dim3(NANG, NBAT), 128>>>(sino);
    backproj_kernel<<<dim3(IMG / 32, IMG / 32), 256>>>(out);
}

// round 12
// speedup vs baseline: 1.5741x; 1.0218x over previous
#include <cuda_runtime.h>
#include <cuda_fp16.h>
#include <cstdint>
#include <math.h>

#define IMG   512
#define NANG  180
#define NBAT  4
#define CH    4            // angles per staged chunk (double-buffered)
#define NC    (NANG / CH)
#define GROW  704          // padded global row (sample-quads): 64 zeros | 512 data | 128 zeros

// ---------------- scratch (no allocations allowed) ----------------
__device__ float  g_ff[IMG];                              // frequency-domain filter
__device__ float  g_h[IMG];                               // spatial filter kernel
__device__ float2 g_trig[NANG];                           // (sin, cos) per angle
__device__ __align__(16) __half g_filth[NANG][GROW * 4];  // filtered rows, fp16 batch-quads, padded

__device__ __forceinline__ void cp_async16(unsigned int smem_addr, const void* gptr) {
    asm volatile("cp.async.ca.shared.global [%0], [%1], 16;\n"
                 :: "r"(smem_addr), "l"(gptr) : "memory");
}
__device__ __forceinline__ void cp_async_commit() {
    asm volatile("cp.async.commit_group;\n" ::: "memory");
}
template <int N>
__device__ __forceinline__ void cp_async_wait() {
    asm volatile("cp.async.wait_group %0;\n" :: "n"(N) : "memory");
}

// ---------------- setup stage 1: ff[k] = 2*Re(fft(f))[k] * sinc window ----------------
__global__ void setup_ff() {                // grid 16, block 32
    __shared__ float s_fj[256];             // f[2i+1] table, computed cooperatively
    const int t = threadIdx.x;
    const int k = blockIdx.x * 32 + t;
    #pragma unroll
    for (int i = 0; i < 8; ++i) {
        int jidx = t * 8 + i;               // j = 2*jidx+1
        int jj = 2 * jidx + 1;
        int m = (jj <= 255) ? jj : (IMG - jj);
        float pm = (float)M_PI * (float)m;
        s_fj[jidx] = -1.0f / (pm * pm);
    }
    __syncthreads();

    float a0 = 0.f, a1 = 0.f, a2 = 0.f, a3 = 0.f;   // 4-way ILP
    for (int ji = 0; ji < 256; ji += 4) {
        #pragma unroll
        for (int u = 0; u < 4; ++u) {
            int jj = 2 * (ji + u) + 1;
            int idx = (jj * k) & (IMG - 1);
            float c = cospif((float)idx * (1.0f / 256.0f));
            float fj = s_fj[ji + u];
            if (u == 0) a0 = fmaf(fj, c, a0);
            else if (u == 1) a1 = fmaf(fj, c, a1);
            else if (u == 2) a2 = fmaf(fj, c, a2);
            else a3 = fmaf(fj, c, a3);
        }
    }
    float ffk = 2.0f * (0.25f + ((a0 + a1) + (a2 + a3)));
    if (k > 0) {
        int m = (k <= 256) ? k : (IMG - k);          // |fftfreq|*N
        float x = (float)m * (1.0f / (float)IMG);    // exact
        ffk *= sinpif(x) / ((float)M_PI * x);        // sin(omega)/omega, even
    }
    g_ff[k] = ffk;
    if (k < NANG) {
        double th = (double)k * (M_PI / 179.0);      // linspace(0,180,180) deg
        g_trig[k] = make_float2((float)sin(th), (float)cos(th));
    }
}

// ---------------- setup stage 2: h = ifft(ff) (cosine DFT), ff cached in smem ----------------
__global__ void setup_h() {                 // grid 16, block 32
    __shared__ float s_ff[IMG];
    const int t = threadIdx.x;
    const int q = blockIdx.x * 32 + t;
    #pragma unroll
    for (int i = 0; i < 4; ++i)
        reinterpret_cast<float4*>(s_ff)[i * 32 + t] = reinterpret_cast<const float4*>(g_ff)[i * 32 + t];
    __syncthreads();

    float a0 = 0.f, a1 = 0.f, a2 = 0.f, a3 = 0.f;
    for (int k = 0; k < IMG; k += 4) {
        #pragma unroll
        for (int u = 0; u < 4; ++u) {
            int idx = ((k + u) * q) & (IMG - 1);
            float c = cospif((float)idx * (1.0f / 256.0f));
            float v = s_ff[k + u];
            if (u == 0) a0 = fmaf(v, c, a0);
            else if (u == 1) a1 = fmaf(v, c, a1);
            else if (u == 2) a2 = fmaf(v, c, a2);
            else a3 = fmaf(v, c, a3);
        }
    }
    g_h[q] = ((a0 + a1) + (a2 + a3)) * (1.0f / (float)IMG);
}

// ---------------- filtering: circular conv + write padded fp16 batch-quad rows ----------------
__global__ void filter_kernel(const float* __restrict__ sino) {
    __shared__ float s_row[2 * IMG];   // row duplicated -> no modulo
    __shared__ float s_hr[IMG];
    const int a = blockIdx.x;
    const int b = blockIdx.y;
    const int t = threadIdx.x;         // 0..127

    float4 r4 = reinterpret_cast<const float4*>(sino + (b * NANG + a) * IMG)[t];
    reinterpret_cast<float4*>(s_row)[t]       = r4;
    reinterpret_cast<float4*>(s_row)[t + 128] = r4;

    float4 h4 = reinterpret_cast<const float4*>(g_h)[t];   // h[4t..4t+3]
    s_hr[(IMG - (4 * t + 0)) & (IMG - 1)] = h4.x;
    s_hr[(IMG - (4 * t + 1)) & (IMG - 1)] = h4.y;
    s_hr[(IMG - (4 * t + 2)) & (IMG - 1)] = h4.z;
    s_hr[(IMG - (4 * t + 3)) & (IMG - 1)] = h4.w;

    // zero the global pads (sample-quads, 8B each) for this angle
    uint2* rowq = reinterpret_cast<uint2*>(&g_filth[a][0]);
    if (b == 0) {
        if (t < 64) rowq[t] = make_uint2(0u, 0u);            // samples 0..63
    } else if (b == 1) {
        rowq[576 + t] = make_uint2(0u, 0u);                  // samples 576..703
    }
    __syncthreads();

    float acc0 = 0.f, acc1 = 0.f, acc2 = 0.f, acc3 = 0.f;
    const int obase = 4 * t;
    float4 R0 = *reinterpret_cast<const float4*>(&s_row[obase]);
    #pragma unroll 4
    for (int u = 0; u < IMG; u += 4) {
        float4 HR = *reinterpret_cast<const float4*>(&s_hr[u]);                   // broadcast
        float4 R1 = *reinterpret_cast<const float4*>(&s_row[obase + u + 4]);      // sliding
        acc0 = fmaf(R0.x, HR.x, fmaf(R0.y, HR.y, fmaf(R0.z, HR.z, fmaf(R0.w, HR.w, acc0))));
        acc1 = fmaf(R0.y, HR.x, fmaf(R0.z, HR.y, fmaf(R0.w, HR.z, fmaf(R1.x, HR.w, acc1))));
        acc2 = fmaf(R0.z, HR.x, fmaf(R0.w, HR.y, fmaf(R1.x, HR.z, fmaf(R1.y, HR.w, acc2))));
        acc3 = fmaf(R0.w, HR.x, fmaf(R1.x, HR.y, fmaf(R1.y, HR.z, fmaf(R1.z, HR.w, acc3))));
        R0 = R1;
    }

    // scatter into fp16 batch-quad layout: sample (64+obase+i), component b
    __half* dsth = &g_filth[a][64 * 4];
    dsth[(obase + 0) * 4 + b] = __float2half_rn(acc0);
    dsth[(obase + 1) * 4 + b] = __float2half_rn(acc1);
    dsth[(obase + 2) * 4 + b] = __float2half_rn(acc2);
    dsth[(obase + 3) * 4 + b] = __float2half_rn(acc3);
}

// ---------------- backprojection: 32x32 tile / 512 threads, 2 px/thread, fp16 windows ------
// Per (block, angle): stage 64 fp16 sample-quads from base-2 (base = floor(p_min_tile) & ~1).
// Surviving tiles intersect the circle -> p_min >= -46; span < 45 -> window covers both taps;
// zeros come from the global pads. Metadata (sin, cos, 258-base) published via smem float4.
__global__ __launch_bounds__(512) void backproj_kernel(float* __restrict__ out) {
    __shared__ uint2  s_win[2][CH][64];     // 4 KB, double-buffered fp16 windows
    __shared__ float4 s_meta[2][CH];        // (sin, cos, offset, -)
    __shared__ float2 s_trig[NANG];

    const int t  = threadIdx.x;
    const int tx = t & 31;
    const int ty = t >> 5;             // 0..15
    const int w  = blockIdx.x * 32 + tx;
    const int y0 = blockIdx.y * 32 + ty;

    const float xf  = 255.0f - (float)w;
    const float yfa = (float)y0 - 256.0f;
    const float yfb = (float)(y0 + 16) - 256.0f;

    // block-level circle early-out (tile entirely outside radius 256)
    {
        float xhi = 255.0f - (float)(blockIdx.x * 32);
        float xlo = xhi - 31.0f;
        float ylo = (float)(blockIdx.y * 32) - 256.0f;
        float yhi = ylo + 31.0f;
        float mx = (xlo <= 0.0f && 0.0f <= xhi) ? 0.0f : fminf(fabsf(xlo), fabsf(xhi));
        float my = (ylo <= 0.0f && 0.0f <= yhi) ? 0.0f : fminf(fabsf(ylo), fabsf(yhi));
        if (fmaf(mx, mx, my * my) > 65536.0f) {
            #pragma unroll
            for (int k = 0; k < 2; ++k) {
                int pix = (y0 + 16 * k) * IMG + w;
                out[0 * IMG * IMG + pix] = 0.0f;
                out[1 * IMG * IMG + pix] = 0.0f;
                out[2 * IMG * IMG + pix] = 0.0f;
                out[3 * IMG * IMG + pix] = 0.0f;
            }
            return;
        }
    }

    if (t < NANG) s_trig[t] = g_trig[t];
    __syncthreads();                   // trig visible before staging

    const float xfmin = 224.0f - 32.0f * (float)blockIdx.x;
    const float yfmin = 32.0f * (float)blockIdx.y - 256.0f;
    const float yfmax = yfmin + 31.0f;

    const unsigned int sbase = (unsigned int)__cvta_generic_to_shared(&s_win[0][0][0]);

    const int st_ang = t >> 5;         // 0..3 for t < 128
    const int st_j   = t & 31;         // 0..31, each covers 2 sample-quads (16B)

    auto stage = [&](int c, int buf) {
        if (t < CH * 32) {
            float2 sc = s_trig[c * CH + st_ang];
            float t0  = fmaf(xfmin, sc.x, 256.0f);
            float pmw = fminf(fmaf(yfmin, sc.y, t0), fmaf(yfmax, sc.y, t0));
            int base  = ((int)floorf(pmw)) & ~1;      // even -> 16B-aligned window start
            const __half* src = &g_filth[c * CH + st_ang][(64 + base - 2 + 2 * st_j) * 4];
            unsigned int dst = sbase + (unsigned int)(((buf * CH + st_ang) * 64 + 2 * st_j) * 8);
            cp_async16(dst, src);
            if (st_j == 0)
                s_meta[buf][st_ang] = make_float4(sc.x, sc.y, 258.0f - (float)base, 0.f);
            cp_async_commit();
        }
    };

    stage(0, 0);

    float ac0[4] = {0.f, 0.f, 0.f, 0.f};   // pixel a (y0)
    float ac1[4] = {0.f, 0.f, 0.f, 0.f};   // pixel b (y0+16)

    for (int c = 0; c < NC; ++c) {
        if (c + 1 < NC) { stage(c + 1, (c + 1) & 1); cp_async_wait<1>(); }
        else            { cp_async_wait<0>(); }
        __syncthreads();

        #pragma unroll
        for (int ci = 0; ci < CH; ++ci) {
            const float4 m  = s_meta[c & 1][ci];        // sin, cos, offset
            const float  pq = fmaf(xf, m.x, m.z);
            const uint2* win = s_win[c & 1][ci];

            // pixel a
            {
                float q  = fmaf(yfa, m.y, pq);
                float fl = floorf(q);
                float fr = q - fl;
                float om = 1.0f - fr;
                int   il = (int)fl;
                uint2 u0 = win[il];
                uint2 u1 = win[il + 1];
                float2 v0a = __half22float2(*reinterpret_cast<__half2*>(&u0.x));
                float2 v0b = __half22float2(*reinterpret_cast<__half2*>(&u0.y));
                float2 v1a = __half22float2(*reinterpret_cast<__half2*>(&u1.x));
                float2 v1b = __half22float2(*reinterpret_cast<__half2*>(&u1.y));
                ac0[0] = fmaf(om, v0a.x, fmaf(fr, v1a.x, ac0[0]));
                ac0[1] = fmaf(om, v0a.y, fmaf(fr, v1a.y, ac0[1]));
                ac0[2] = fmaf(om, v0b.x, fmaf(fr, v1b.x, ac0[2]));
                ac0[3] = fmaf(om, v0b.y, fmaf(fr, v1b.y, ac0[3]));
            }
            // pixel b
            {
                float q  = fmaf(yfb, m.y, pq);
                float fl = floorf(q);
                float fr = q - fl;
                float om = 1.0f - fr;
                int   il = (int)fl;
                uint2 u0 = win[il];
                uint2 u1 = win[il + 1];
                float2 v0a = __half22float2(*reinterpret_cast<__half2*>(&u0.x));
                float2 v0b = __half22float2(*reinterpret_cast<__half2*>(&u0.y));
                float2 v1a = __half22float2(*reinterpret_cast<__half2*>(&u1.x));
                float2 v1b = __half22float2(*reinterpret_cast<__half2*>(&u1.y));
                ac1[0] = fmaf(om, v0a.x, fmaf(fr, v1a.x, ac1[0]));
                ac1[1] = fmaf(om, v0a.y, fmaf(fr, v1a.y, ac1[1]));
                ac1[2] = fmaf(om, v0b.x, fmaf(fr, v1b.x, ac1[2]));
                ac1[3] = fmaf(om, v0b.y, fmaf(fr, v1b.y, ac1[3]));
            }
        }
        __syncthreads();               // protect windows/meta before next overwrite
    }

    const float gscale = (float)(M_PI / (2.0 * NANG));
    {
        const bool inside = fmaf(xf, xf, yfa * yfa) <= 65536.0f;
        const float g = inside ? gscale : 0.0f;
        const int pix = y0 * IMG + w;
        out[0 * IMG * IMG + pix] = ac0[0] * g;
        out[1 * IMG * IMG + pix] = ac0[1] * g;
        out[2 * IMG * IMG + pix] = ac0[2] * g;
        out[3 * IMG * IMG + pix] = ac0[3] * g;
    }
    {
        const bool inside = fmaf(xf, xf, yfb * yfb) <= 65536.0f;
        const float g = inside ? gscale : 0.0f;
        const int pix = (y0 + 16) * IMG + w;
        out[0 * IMG * IMG + pix] = ac1[0] * g;
        out[1 * IMG * IMG + pix] = ac1[1] * g;
        out[2 * IMG * IMG + pix] = ac1[2] * g;
        out[3 * IMG * IMG + pix] = ac1[3] * g;
    }
}

// ---------------- launcher ----------------
extern "C" void kernel_launch(void* const* d_in, const int* in_sizes, int n_in,
                              void* d_out, int out_size) {
    const float* sino = (const float*)d_in[0];
    float* out = (float*)d_out;

    setup_ff<<<16, 32>>>();
    setup_h<<<16, 32>>>();
    filter_kernel<<<dim3(NANG, NBAT), 128>>>(sino);
    backproj_kernel<<<dim3(IMG / 32, IMG / 32), 512>>>(out);
}

// round 14
// speedup vs baseline: 1.6934x; 1.0758x over previous
#include <cuda_runtime.h>
#include <cuda_fp16.h>
#include <cstdint>
#include <math.h>

#define IMG   512
#define NANG  180
#define NBAT  4
#define HANG  90           // angles per z-half
#define CH    2            // angles per staged chunk (double-buffered)
#define NCZ   (HANG / CH)  // 45 chunks per half
#define GROW  704          // padded global row (sample-quads): 64 zeros | 512 data | 128 zeros

// ---------------- scratch (no allocations allowed) ----------------
__device__ float  g_ff[IMG];                              // frequency-domain filter
__device__ float  g_h[IMG];                               // spatial filter kernel
__device__ float2 g_trig[NANG];                           // (sin, cos) per angle
__device__ __align__(16) __half g_filth[NANG][GROW * 4];  // filtered rows, fp16 batch-quads, padded
__device__ __align__(16) float4 g_part[2][IMG * IMG];     // per-half partial sums (batch-quads)

__device__ __forceinline__ void cp_async16(unsigned int smem_addr, const void* gptr) {
    asm volatile("cp.async.ca.shared.global [%0], [%1], 16;\n"
                 :: "r"(smem_addr), "l"(gptr) : "memory");
}
__device__ __forceinline__ void cp_async_commit() {
    asm volatile("cp.async.commit_group;\n" ::: "memory");
}
template <int N>
__device__ __forceinline__ void cp_async_wait() {
    asm volatile("cp.async.wait_group %0;\n" :: "n"(N) : "memory");
}

// ---------------- setup stage 1: ff[k] = 2*Re(fft(f))[k] * sinc window ----------------
__global__ void setup_ff() {                // grid 16, block 32
    __shared__ float s_fj[256];             // f[2i+1] table, computed cooperatively
    const int t = threadIdx.x;
    const int k = blockIdx.x * 32 + t;
    #pragma unroll
    for (int i = 0; i < 8; ++i) {
        int jidx = t * 8 + i;               // j = 2*jidx+1
        int jj = 2 * jidx + 1;
        int m = (jj <= 255) ? jj : (IMG - jj);
        float pm = (float)M_PI * (float)m;
        s_fj[jidx] = -1.0f / (pm * pm);
    }
    __syncthreads();

    float a0 = 0.f, a1 = 0.f, a2 = 0.f, a3 = 0.f;   // 4-way ILP
    for (int ji = 0; ji < 256; ji += 4) {
        #pragma unroll
        for (int u = 0; u < 4; ++u) {
            int jj = 2 * (ji + u) + 1;
            int idx = (jj * k) & (IMG - 1);
            float c = cospif((float)idx * (1.0f / 256.0f));
            float fj = s_fj[ji + u];
            if (u == 0) a0 = fmaf(fj, c, a0);
            else if (u == 1) a1 = fmaf(fj, c, a1);
            else if (u == 2) a2 = fmaf(fj, c, a2);
            else a3 = fmaf(fj, c, a3);
        }
    }
    float ffk = 2.0f * (0.25f + ((a0 + a1) + (a2 + a3)));
    if (k > 0) {
        int m = (k <= 256) ? k : (IMG - k);          // |fftfreq|*N
        float x = (float)m * (1.0f / (float)IMG);    // exact
        ffk *= sinpif(x) / ((float)M_PI * x);        // sin(omega)/omega, even
    }
    g_ff[k] = ffk;
    if (k < NANG) {
        double th = (double)k * (M_PI / 179.0);      // linspace(0,180,180) deg
        g_trig[k] = make_float2((float)sin(th), (float)cos(th));
    }
}

// ---------------- setup stage 2: h = ifft(ff) (cosine DFT), ff cached in smem ----------------
__global__ void setup_h() {                 // grid 16, block 32
    __shared__ float s_ff[IMG];
    const int t = threadIdx.x;
    const int q = blockIdx.x * 32 + t;
    #pragma unroll
    for (int i = 0; i < 4; ++i)
        reinterpret_cast<float4*>(s_ff)[i * 32 + t] = reinterpret_cast<const float4*>(g_ff)[i * 32 + t];
    __syncthreads();

    float a0 = 0.f, a1 = 0.f, a2 = 0.f, a3 = 0.f;
    for (int k = 0; k < IMG; k += 4) {
        #pragma unroll
        for (int u = 0; u < 4; ++u) {
            int idx = ((k + u) * q) & (IMG - 1);
            float c = cospif((float)idx * (1.0f / 256.0f));
            float v = s_ff[k + u];
            if (u == 0) a0 = fmaf(v, c, a0);
            else if (u == 1) a1 = fmaf(v, c, a1);
            else if (u == 2) a2 = fmaf(v, c, a2);
            else a3 = fmaf(v, c, a3);
        }
    }
    g_h[q] = ((a0 + a1) + (a2 + a3)) * (1.0f / (float)IMG);
}

// ---------------- filtering: circular conv + write padded fp16 batch-quad rows ----------------
__global__ void filter_kernel(const float* __restrict__ sino) {
    __shared__ float s_row[2 * IMG];   // row duplicated -> no modulo
    __shared__ float s_hr[IMG];
    const int a = blockIdx.x;
    const int b = blockIdx.y;
    const int t = threadIdx.x;         // 0..127

    float4 r4 = reinterpret_cast<const float4*>(sino + (b * NANG + a) * IMG)[t];
    reinterpret_cast<float4*>(s_row)[t]       = r4;
    reinterpret_cast<float4*>(s_row)[t + 128] = r4;

    float4 h4 = reinterpret_cast<const float4*>(g_h)[t];   // h[4t..4t+3]
    s_hr[(IMG - (4 * t + 0)) & (IMG - 1)] = h4.x;
    s_hr[(IMG - (4 * t + 1)) & (IMG - 1)] = h4.y;
    s_hr[(IMG - (4 * t + 2)) & (IMG - 1)] = h4.z;
    s_hr[(IMG - (4 * t + 3)) & (IMG - 1)] = h4.w;

    // zero the global pads (sample-quads, 8B each) for this angle
    uint2* rowq = reinterpret_cast<uint2*>(&g_filth[a][0]);
    if (b == 0) {
        if (t < 64) rowq[t] = make_uint2(0u, 0u);            // samples 0..63
    } else if (b == 1) {
        rowq[576 + t] = make_uint2(0u, 0u);                  // samples 576..703
    }
    __syncthreads();

    float acc0 = 0.f, acc1 = 0.f, acc2 = 0.f, acc3 = 0.f;
    const int obase = 4 * t;
    float4 R0 = *reinterpret_cast<const float4*>(&s_row[obase]);
    #pragma unroll 4
    for (int u = 0; u < IMG; u += 4) {
        float4 HR = *reinterpret_cast<const float4*>(&s_hr[u]);                   // broadcast
        float4 R1 = *reinterpret_cast<const float4*>(&s_row[obase + u + 4]);      // sliding
        acc0 = fmaf(R0.x, HR.x, fmaf(R0.y, HR.y, fmaf(R0.z, HR.z, fmaf(R0.w, HR.w, acc0))));
        acc1 = fmaf(R0.y, HR.x, fmaf(R0.z, HR.y, fmaf(R0.w, HR.z, fmaf(R1.x, HR.w, acc1))));
        acc2 = fmaf(R0.z, HR.x, fmaf(R0.w, HR.y, fmaf(R1.x, HR.z, fmaf(R1.y, HR.w, acc2))));
        acc3 = fmaf(R0.w, HR.x, fmaf(R1.x, HR.y, fmaf(R1.y, HR.z, fmaf(R1.z, HR.w, acc3))));
        R0 = R1;
    }

    // scatter into fp16 batch-quad layout: sample (64+obase+i), component b
    __half* dsth = &g_filth[a][64 * 4];
    dsth[(obase + 0) * 4 + b] = __float2half_rn(acc0);
    dsth[(obase + 1) * 4 + b] = __float2half_rn(acc1);
    dsth[(obase + 2) * 4 + b] = __float2half_rn(acc2);
    dsth[(obase + 3) * 4 + b] = __float2half_rn(acc3);
}

// ---------------- backprojection: 32x32 tile, grid.z=2 angle halves, fp16 windows ----------
// Each z-half accumulates 90 angles into g_part[z]. Early-out tiles write nothing;
// all their pixels are outside the circle, so reduce masks them to exactly 0.
__global__ __launch_bounds__(512) void backproj_kernel() {
    __shared__ uint2  s_win[2][CH][64];     // 2 KB, double-buffered fp16 windows
    __shared__ float4 s_meta[2][CH];        // (sin, cos, offset, -)
    __shared__ float2 s_trig[HANG];

    const int t  = threadIdx.x;
    const int tx = t & 31;
    const int ty = t >> 5;             // 0..15
    const int w  = blockIdx.x * 32 + tx;
    const int y0 = blockIdx.y * 32 + ty;
    const int az0 = blockIdx.z * HANG;

    const float xf  = 255.0f - (float)w;
    const float yfa = (float)y0 - 256.0f;
    const float yfb = (float)(y0 + 16) - 256.0f;

    // block-level circle early-out (tile entirely outside radius 256)
    {
        float xhi = 255.0f - (float)(blockIdx.x * 32);
        float xlo = xhi - 31.0f;
        float ylo = (float)(blockIdx.y * 32) - 256.0f;
        float yhi = ylo + 31.0f;
        float mx = (xlo <= 0.0f && 0.0f <= xhi) ? 0.0f : fminf(fabsf(xlo), fabsf(xhi));
        float my = (ylo <= 0.0f && 0.0f <= yhi) ? 0.0f : fminf(fabsf(ylo), fabsf(yhi));
        if (fmaf(mx, mx, my * my) > 65536.0f) return;   // reduce kernel masks these pixels
    }

    if (t < HANG) s_trig[t] = g_trig[az0 + t];
    __syncthreads();                   // trig visible before staging

    const float xfmin = 224.0f - 32.0f * (float)blockIdx.x;
    const float yfmin = 32.0f * (float)blockIdx.y - 256.0f;
    const float yfmax = yfmin + 31.0f;

    const unsigned int sbase = (unsigned int)__cvta_generic_to_shared(&s_win[0][0][0]);

    const int st_ang = t >> 5;         // 0..1 for t < 64
    const int st_j   = t & 31;         // 0..31, each covers 2 sample-quads (16B)

    auto stage = [&](int c, int buf) {
        if (t < CH * 32) {
            float2 sc = s_trig[c * CH + st_ang];
            float t0  = fmaf(xfmin, sc.x, 256.0f);
            float pmw = fminf(fmaf(yfmin, sc.y, t0), fmaf(yfmax, sc.y, t0));
            int base  = ((int)floorf(pmw)) & ~1;      // even -> 16B-aligned window start
            const __half* src = &g_filth[az0 + c * CH + st_ang][(64 + base - 2 + 2 * st_j) * 4];
            unsigned int dst = sbase + (unsigned int)(((buf * CH + st_ang) * 64 + 2 * st_j) * 8);
            cp_async16(dst, src);
            if (st_j == 0)
                s_meta[buf][st_ang] = make_float4(sc.x, sc.y, 258.0f - (float)base, 0.f);
            cp_async_commit();
        }
    };

    stage(0, 0);

    float ac0[4] = {0.f, 0.f, 0.f, 0.f};   // pixel a (y0)
    float ac1[4] = {0.f, 0.f, 0.f, 0.f};   // pixel b (y0+16)

    for (int c = 0; c < NCZ; ++c) {
        if (c + 1 < NCZ) { stage(c + 1, (c + 1) & 1); cp_async_wait<1>(); }
        else             { cp_async_wait<0>(); }
        __syncthreads();

        #pragma unroll
        for (int ci = 0; ci < CH; ++ci) {
            const float4 m  = s_meta[c & 1][ci];        // sin, cos, offset
            const float  pq = fmaf(xf, m.x, m.z);
            const uint2* win = s_win[c & 1][ci];

            // pixel a
            {
                float q  = fmaf(yfa, m.y, pq);
                float fl = floorf(q);
                float fr = q - fl;
                float om = 1.0f - fr;
                int   il = (int)fl;
                uint2 u0 = win[il];
                uint2 u1 = win[il + 1];
                float2 v0a = __half22float2(*reinterpret_cast<__half2*>(&u0.x));
                float2 v0b = __half22float2(*reinterpret_cast<__half2*>(&u0.y));
                float2 v1a = __half22float2(*reinterpret_cast<__half2*>(&u1.x));
                float2 v1b = __half22float2(*reinterpret_cast<__half2*>(&u1.y));
                ac0[0] = fmaf(om, v0a.x, fmaf(fr, v1a.x, ac0[0]));
                ac0[1] = fmaf(om, v0a.y, fmaf(fr, v1a.y, ac0[1]));
                ac0[2] = fmaf(om, v0b.x, fmaf(fr, v1b.x, ac0[2]));
                ac0[3] = fmaf(om, v0b.y, fmaf(fr, v1b.y, ac0[3]));
            }
            // pixel b
            {
                float q  = fmaf(yfb, m.y, pq);
                float fl = floorf(q);
                float fr = q - fl;
                float om = 1.0f - fr;
                int   il = (int)fl;
                uint2 u0 = win[il];
                uint2 u1 = win[il + 1];
                float2 v0a = __half22float2(*reinterpret_cast<__half2*>(&u0.x));
                float2 v0b = __half22float2(*reinterpret_cast<__half2*>(&u0.y));
                float2 v1a = __half22float2(*reinterpret_cast<__half2*>(&u1.x));
                float2 v1b = __half22float2(*reinterpret_cast<__half2*>(&u1.y));
                ac1[0] = fmaf(om, v0a.x, fmaf(fr, v1a.x, ac1[0]));
                ac1[1] = fmaf(om, v0a.y, fmaf(fr, v1a.y, ac1[1]));
                ac1[2] = fmaf(om, v0b.x, fmaf(fr, v1b.x, ac1[2]));
                ac1[3] = fmaf(om, v0b.y, fmaf(fr, v1b.y, ac1[3]));
            }
        }
        __syncthreads();               // protect windows/meta before next overwrite
    }

    g_part[blockIdx.z][y0 * IMG + w]        = make_float4(ac0[0], ac0[1], ac0[2], ac0[3]);
    g_part[blockIdx.z][(y0 + 16) * IMG + w] = make_float4(ac1[0], ac1[1], ac1[2], ac1[3]);
}

// ---------------- reduce: add halves, apply circle mask + pi/(2A), planar output ----------
__global__ __launch_bounds__(512) void reduce_kernel(float* __restrict__ out) {
    const int pix = blockIdx.x * 512 + threadIdx.x;
    const float4 p0 = g_part[0][pix];
    const float4 p1 = g_part[1][pix];
    const int x = pix & (IMG - 1);
    const int y = pix >> 9;
    const float xf = 255.0f - (float)x;
    const float yf = (float)y - 256.0f;
    const float g = (fmaf(xf, xf, yf * yf) <= 65536.0f) ? (float)(M_PI / (2.0 * NANG)) : 0.0f;
    out[0 * IMG * IMG + pix] = (p0.x + p1.x) * g;
    out[1 * IMG * IMG + pix] = (p0.y + p1.y) * g;
    out[2 * IMG * IMG + pix] = (p0.z + p1.z) * g;
    out[3 * IMG * IMG + pix] = (p0.w + p1.w) * g;
}

// ---------------- launcher ----------------
extern "C" void kernel_launch(void* const* d_in, const int* in_sizes, int n_in,
                              void* d_out, int out_size) {
    const float* sino = (const float*)d_in[0];
    float* out = (float*)d_out;

    setup_ff<<<16, 32>>>();
    setup_h<<<16, 32>>>();
    filter_kernel<<<dim3(NANG, NBAT), 128>>>(sino);
    backproj_kernel<<<dim3(IMG / 32, IMG / 32, 2), 512>>>();
    reduce_kernel<<<IMG * IMG / 512, 512>>>(out);
}

// round 15
// speedup vs baseline: 1.8368x; 1.0846x over previous
#include <cuda_runtime.h>
#include <cuda_fp16.h>
#include <cstdint>
#include <math.h>

#define IMG   512
#define NANG  180
#define NBAT  4
#define NZ    4            // angle splits
#define HANG  (NANG / NZ)  // 45 angles per z-slice
#define CH    3            // angles per staged chunk (double-buffered), 45 % 3 == 0
#define NCZ   (HANG / CH)  // 15 chunks per slice
#define GROW  704          // padded global row (sample-quads): 64 zeros | 512 data | 128 zeros

// ---------------- scratch (no allocations allowed) ----------------
__device__ float  g_ff[IMG];                              // frequency-domain filter
__device__ float  g_h[IMG];                               // spatial filter kernel
__device__ float2 g_trig[NANG];                           // (sin, cos) per angle
__device__ __align__(16) __half g_filth[NANG][GROW * 4];  // filtered rows, fp16 batch-quads, padded
__device__ __align__(16) float4 g_part[NZ][IMG * IMG];    // per-slice partial sums (batch-quads)

__device__ __forceinline__ void cp_async16(unsigned int smem_addr, const void* gptr) {
    asm volatile("cp.async.ca.shared.global [%0], [%1], 16;\n"
                 :: "r"(smem_addr), "l"(gptr) : "memory");
}
__device__ __forceinline__ void cp_async_commit() {
    asm volatile("cp.async.commit_group;\n" ::: "memory");
}
template <int N>
__device__ __forceinline__ void cp_async_wait() {
    asm volatile("cp.async.wait_group %0;\n" :: "n"(N) : "memory");
}
// packed f32x2 accumulate: a += b (single FFMA-pipe op on sm_103a)
__device__ __forceinline__ void addf32x2(float2& a, float2 b) {
    unsigned long long ua = reinterpret_cast<unsigned long long&>(a);
    unsigned long long ub = reinterpret_cast<unsigned long long&>(b);
    asm("add.rn.f32x2 %0, %1, %2;" : "=l"(ua) : "l"(ua), "l"(ub));
    reinterpret_cast<unsigned long long&>(a) = ua;
}

// ---------------- setup stage 1: ff[k] = 2*Re(fft(f))[k] * sinc window ----------------
__global__ void setup_ff() {                // grid 16, block 32
    __shared__ float s_fj[256];             // f[2i+1] table, computed cooperatively
    const int t = threadIdx.x;
    const int k = blockIdx.x * 32 + t;
    #pragma unroll
    for (int i = 0; i < 8; ++i) {
        int jidx = t * 8 + i;               // j = 2*jidx+1
        int jj = 2 * jidx + 1;
        int m = (jj <= 255) ? jj : (IMG - jj);
        float pm = (float)M_PI * (float)m;
        s_fj[jidx] = -1.0f / (pm * pm);
    }
    __syncthreads();

    float a0 = 0.f, a1 = 0.f, a2 = 0.f, a3 = 0.f;   // 4-way ILP
    for (int ji = 0; ji < 256; ji += 4) {
        #pragma unroll
        for (int u = 0; u < 4; ++u) {
            int jj = 2 * (ji + u) + 1;
            int idx = (jj * k) & (IMG - 1);
            float c = cospif((float)idx * (1.0f / 256.0f));
            float fj = s_fj[ji + u];
            if (u == 0) a0 = fmaf(fj, c, a0);
            else if (u == 1) a1 = fmaf(fj, c, a1);
            else if (u == 2) a2 = fmaf(fj, c, a2);
            else a3 = fmaf(fj, c, a3);
        }
    }
    float ffk = 2.0f * (0.25f + ((a0 + a1) + (a2 + a3)));
    if (k > 0) {
        int m = (k <= 256) ? k : (IMG - k);          // |fftfreq|*N
        float x = (float)m * (1.0f / (float)IMG);    // exact
        ffk *= sinpif(x) / ((float)M_PI * x);        // sin(omega)/omega, even
    }
    g_ff[k] = ffk;
    if (k < NANG) {
        double th = (double)k * (M_PI / 179.0);      // linspace(0,180,180) deg
        g_trig[k] = make_float2((float)sin(th), (float)cos(th));
    }
}

// ---------------- setup stage 2: h = ifft(ff) (cosine DFT), ff cached in smem ----------------
__global__ void setup_h() {                 // grid 16, block 32
    __shared__ float s_ff[IMG];
    const int t = threadIdx.x;
    const int q = blockIdx.x * 32 + t;
    #pragma unroll
    for (int i = 0; i < 4; ++i)
        reinterpret_cast<float4*>(s_ff)[i * 32 + t] = reinterpret_cast<const float4*>(g_ff)[i * 32 + t];
    __syncthreads();

    float a0 = 0.f, a1 = 0.f, a2 = 0.f, a3 = 0.f;
    for (int k = 0; k < IMG; k += 4) {
        #pragma unroll
        for (int u = 0; u < 4; ++u) {
            int idx = ((k + u) * q) & (IMG - 1);
            float c = cospif((float)idx * (1.0f / 256.0f));
            float v = s_ff[k + u];
            if (u == 0) a0 = fmaf(v, c, a0);
            else if (u == 1) a1 = fmaf(v, c, a1);
            else if (u == 2) a2 = fmaf(v, c, a2);
            else a3 = fmaf(v, c, a3);
        }
    }
    g_h[q] = ((a0 + a1) + (a2 + a3)) * (1.0f / (float)IMG);
}

// ---------------- filtering: circular conv + write padded fp16 batch-quad rows ----------------
__global__ void filter_kernel(const float* __restrict__ sino) {
    __shared__ float s_row[2 * IMG];   // row duplicated -> no modulo
    __shared__ float s_hr[IMG];
    const int a = blockIdx.x;
    const int b = blockIdx.y;
    const int t = threadIdx.x;         // 0..127

    float4 r4 = reinterpret_cast<const float4*>(sino + (b * NANG + a) * IMG)[t];
    reinterpret_cast<float4*>(s_row)[t]       = r4;
    reinterpret_cast<float4*>(s_row)[t + 128] = r4;

    float4 h4 = reinterpret_cast<const float4*>(g_h)[t];   // h[4t..4t+3]
    s_hr[(IMG - (4 * t + 0)) & (IMG - 1)] = h4.x;
    s_hr[(IMG - (4 * t + 1)) & (IMG - 1)] = h4.y;
    s_hr[(IMG - (4 * t + 2)) & (IMG - 1)] = h4.z;
    s_hr[(IMG - (4 * t + 3)) & (IMG - 1)] = h4.w;

    // zero the global pads (sample-quads, 8B each) for this angle
    uint2* rowq = reinterpret_cast<uint2*>(&g_filth[a][0]);
    if (b == 0) {
        if (t < 64) rowq[t] = make_uint2(0u, 0u);            // samples 0..63
    } else if (b == 1) {
        rowq[576 + t] = make_uint2(0u, 0u);                  // samples 576..703
    }
    __syncthreads();

    float acc0 = 0.f, acc1 = 0.f, acc2 = 0.f, acc3 = 0.f;
    const int obase = 4 * t;
    float4 R0 = *reinterpret_cast<const float4*>(&s_row[obase]);
    #pragma unroll 4
    for (int u = 0; u < IMG; u += 4) {
        float4 HR = *reinterpret_cast<const float4*>(&s_hr[u]);                   // broadcast
        float4 R1 = *reinterpret_cast<const float4*>(&s_row[obase + u + 4]);      // sliding
        acc0 = fmaf(R0.x, HR.x, fmaf(R0.y, HR.y, fmaf(R0.z, HR.z, fmaf(R0.w, HR.w, acc0))));
        acc1 = fmaf(R0.y, HR.x, fmaf(R0.z, HR.y, fmaf(R0.w, HR.z, fmaf(R1.x, HR.w, acc1))));
        acc2 = fmaf(R0.z, HR.x, fmaf(R0.w, HR.y, fmaf(R1.x, HR.z, fmaf(R1.y, HR.w, acc2))));
        acc3 = fmaf(R0.w, HR.x, fmaf(R1.x, HR.y, fmaf(R1.y, HR.z, fmaf(R1.z, HR.w, acc3))));
        R0 = R1;
    }

    // scatter into fp16 batch-quad layout: sample (64+obase+i), component b
    __half* dsth = &g_filth[a][64 * 4];
    dsth[(obase + 0) * 4 + b] = __float2half_rn(acc0);
    dsth[(obase + 1) * 4 + b] = __float2half_rn(acc1);
    dsth[(obase + 2) * 4 + b] = __float2half_rn(acc2);
    dsth[(obase + 3) * 4 + b] = __float2half_rn(acc3);
}

// ---------------- backprojection: 32x32 tile, grid.z=NZ angle slices, fp16 lerp ------------
// Each z-slice accumulates HANG angles into g_part[z]. Early-out tiles write nothing;
// all their pixels are outside the circle, so reduce masks them to exactly 0.
// Lerp computed in half2 (v0 + fr*(v1-v0)), converted once, accumulated via packed f32x2.
__global__ __launch_bounds__(512) void backproj_kernel() {
    __shared__ uint2  s_win[2][CH][64];     // 3 KB, double-buffered fp16 windows
    __shared__ float4 s_meta[2][CH];        // (sin, cos, offset, -)
    __shared__ float2 s_trig[HANG];

    const int t  = threadIdx.x;
    const int tx = t & 31;
    const int ty = t >> 5;             // 0..15
    const int w  = blockIdx.x * 32 + tx;
    const int y0 = blockIdx.y * 32 + ty;
    const int az0 = blockIdx.z * HANG;

    const float xf  = 255.0f - (float)w;
    const float yfa = (float)y0 - 256.0f;
    const float yfb = (float)(y0 + 16) - 256.0f;

    // block-level circle early-out (tile entirely outside radius 256)
    {
        float xhi = 255.0f - (float)(blockIdx.x * 32);
        float xlo = xhi - 31.0f;
        float ylo = (float)(blockIdx.y * 32) - 256.0f;
        float yhi = ylo + 31.0f;
        float mx = (xlo <= 0.0f && 0.0f <= xhi) ? 0.0f : fminf(fabsf(xlo), fabsf(xhi));
        float my = (ylo <= 0.0f && 0.0f <= yhi) ? 0.0f : fminf(fabsf(ylo), fabsf(yhi));
        if (fmaf(mx, mx, my * my) > 65536.0f) return;   // reduce kernel masks these pixels
    }

    if (t < HANG) s_trig[t] = g_trig[az0 + t];
    __syncthreads();                   // trig visible before staging

    const float xfmin = 224.0f - 32.0f * (float)blockIdx.x;
    const float yfmin = 32.0f * (float)blockIdx.y - 256.0f;
    const float yfmax = yfmin + 31.0f;

    const unsigned int sbase = (unsigned int)__cvta_generic_to_shared(&s_win[0][0][0]);

    const int st_ang = t >> 5;         // 0..2 for t < 96
    const int st_j   = t & 31;         // 0..31, each covers 2 sample-quads (16B)

    auto stage = [&](int c, int buf) {
        if (t < CH * 32) {
            float2 sc = s_trig[c * CH + st_ang];
            float t0  = fmaf(xfmin, sc.x, 256.0f);
            float pmw = fminf(fmaf(yfmin, sc.y, t0), fmaf(yfmax, sc.y, t0));
            int base  = ((int)floorf(pmw)) & ~1;      // even -> 16B-aligned window start
            const __half* src = &g_filth[az0 + c * CH + st_ang][(64 + base - 2 + 2 * st_j) * 4];
            unsigned int dst = sbase + (unsigned int)(((buf * CH + st_ang) * 64 + 2 * st_j) * 8);
            cp_async16(dst, src);
            if (st_j == 0)
                s_meta[buf][st_ang] = make_float4(sc.x, sc.y, 258.0f - (float)base, 0.f);
            cp_async_commit();
        }
    };

    stage(0, 0);

    float2 ac0A = {0.f, 0.f}, ac0B = {0.f, 0.f};   // pixel a (y0): batches 01, 23
    float2 ac1A = {0.f, 0.f}, ac1B = {0.f, 0.f};   // pixel b (y0+16)

    for (int c = 0; c < NCZ; ++c) {
        if (c + 1 < NCZ) { stage(c + 1, (c + 1) & 1); cp_async_wait<1>(); }
        else             { cp_async_wait<0>(); }
        __syncthreads();

        #pragma unroll
        for (int ci = 0; ci < CH; ++ci) {
            const float4 m  = s_meta[c & 1][ci];        // sin, cos, offset
            const float  pq = fmaf(xf, m.x, m.z);
            const uint2* win = s_win[c & 1][ci];

            // pixel a
            {
                float q   = fmaf(yfa, m.y, pq);
                float fl  = floorf(q);
                float fr  = q - fl;
                int   il  = (int)fl;
                __half2 fr2 = __float2half2_rn(fr);
                uint2 u0 = win[il];
                uint2 u1 = win[il + 1];
                __half2 v0a = *reinterpret_cast<__half2*>(&u0.x);
                __half2 v0b = *reinterpret_cast<__half2*>(&u0.y);
                __half2 v1a = *reinterpret_cast<__half2*>(&u1.x);
                __half2 v1b = *reinterpret_cast<__half2*>(&u1.y);
                __half2 la = __hfma2(fr2, __hsub2(v1a, v0a), v0a);
                __half2 lb = __hfma2(fr2, __hsub2(v1b, v0b), v0b);
                addf32x2(ac0A, __half22float2(la));
                addf32x2(ac0B, __half22float2(lb));
            }
            // pixel b
            {
                float q   = fmaf(yfb, m.y, pq);
                float fl  = floorf(q);
                float fr  = q - fl;
                int   il  = (int)fl;
                __half2 fr2 = __float2half2_rn(fr);
                uint2 u0 = win[il];
                uint2 u1 = win[il + 1];
                __half2 v0a = *reinterpret_cast<__half2*>(&u0.x);
                __half2 v0b = *reinterpret_cast<__half2*>(&u0.y);
                __half2 v1a = *reinterpret_cast<__half2*>(&u1.x);
                __half2 v1b = *reinterpret_cast<__half2*>(&u1.y);
                __half2 la = __hfma2(fr2, __hsub2(v1a, v0a), v0a);
                __half2 lb = __hfma2(fr2, __hsub2(v1b, v0b), v0b);
                addf32x2(ac1A, __half22float2(la));
                addf32x2(ac1B, __half22float2(lb));
            }
        }
        __syncthreads();               // protect windows/meta before next overwrite
    }

    g_part[blockIdx.z][y0 * IMG + w]        = make_float4(ac0A.x, ac0A.y, ac0B.x, ac0B.y);
    g_part[blockIdx.z][(y0 + 16) * IMG + w] = make_float4(ac1A.x, ac1A.y, ac1B.x, ac1B.y);
}

// ---------------- reduce: add slices, apply circle mask + pi/(2A), planar output ----------
__global__ __launch_bounds__(512) void reduce_kernel(float* __restrict__ out) {
    const int pix = blockIdx.x * 512 + threadIdx.x;
    const float4 p0 = g_part[0][pix];
    const float4 p1 = g_part[1][pix];
    const float4 p2 = g_part[2][pix];
    const float4 p3 = g_part[3][pix];
    const int x = pix & (IMG - 1);
    const int y = pix >> 9;
    const float xf = 255.0f - (float)x;
    const float yf = (float)y - 256.0f;
    const float g = (fmaf(xf, xf, yf * yf) <= 65536.0f) ? (float)(M_PI / (2.0 * NANG)) : 0.0f;
    out[0 * IMG * IMG + pix] = ((p0.x + p1.x) + (p2.x + p3.x)) * g;
    out[1 * IMG * IMG + pix] = ((p0.y + p1.y) + (p2.y + p3.y)) * g;
    out[2 * IMG * IMG + pix] = ((p0.z + p1.z) + (p2.z + p3.z)) * g;
    out[3 * IMG * IMG + pix] = ((p0.w + p1.w) + (p2.w + p3.w)) * g;
}

// ---------------- launcher ----------------
extern "C" void kernel_launch(void* const* d_in, const int* in_sizes, int n_in,
                              void* d_out, int out_size) {
    const float* sino = (const float*)d_in[0];
    float* out = (float*)d_out;

    setup_ff<<<16, 32>>>();
    setup_h<<<16, 32>>>();
    filter_kernel<<<dim3(NANG, NBAT), 128>>>(sino);
    backproj_kernel<<<dim3(IMG / 32, IMG / 32, NZ), 512>>>();
    reduce_kernel<<<IMG * IMG / 512, 512>>>(out);
}

// round 16
// speedup vs baseline: 2.0990x; 1.1428x over previous
#include <cuda_runtime.h>
#include <cuda_fp16.h>
#include <cstdint>
#include <math.h>

#define IMG   512
#define NANG  180
#define NBAT  4
#define NZ    4            // angle splits
#define HANG  (NANG / NZ)  // 45 angles per z-slice
#define CH    3            // angles per staged chunk (double-buffered), 45 % 3 == 0
#define NCZ   (HANG / CH)  // 15 chunks per slice
#define GROW  704          // padded global row slots (uint4 pairs)
#define WSLOT 48           // staged slots per angle (16B each)

// ---------------- scratch (no allocations allowed) ----------------
__device__ float  g_ff[IMG];                            // frequency-domain filter
__device__ float  g_h[IMG];                             // spatial filter kernel
__device__ float2 g_trig[NANG];                         // (sin, cos) per angle
__device__ __align__(16) uint4  g_dup[NANG][GROW];      // fp16 rows, duplicated pairs:
                                                        // slot s = (quad(s), quad(s+1)), quad = 4 fp16 batches
__device__ __align__(16) float4 g_part[NZ][IMG * IMG];  // per-slice partial sums

__device__ __forceinline__ void cp_async16(unsigned int smem_addr, const void* gptr) {
    asm volatile("cp.async.ca.shared.global [%0], [%1], 16;\n"
                 :: "r"(smem_addr), "l"(gptr) : "memory");
}
__device__ __forceinline__ void cp_async_commit() {
    asm volatile("cp.async.commit_group;\n" ::: "memory");
}
template <int N>
__device__ __forceinline__ void cp_async_wait() {
    asm volatile("cp.async.wait_group %0;\n" :: "n"(N) : "memory");
}
// packed f32x2 accumulate: a += b
__device__ __forceinline__ void addf32x2(float2& a, float2 b) {
    unsigned long long ua = reinterpret_cast<unsigned long long&>(a);
    unsigned long long ub = reinterpret_cast<unsigned long long&>(b);
    asm("add.rn.f32x2 %0, %1, %2;" : "=l"(ua) : "l"(ua), "l"(ub));
    reinterpret_cast<unsigned long long&>(a) = ua;
}

// ---------------- setup stage 1: one warp per k ----------------
__global__ void setup_ff() {                // grid 512, block 32
    const int k = blockIdx.x;
    const int t = threadIdx.x;
    float acc = 0.0f;
    #pragma unroll
    for (int i = 0; i < 8; ++i) {
        int jidx = t * 8 + i;               // 0..255, j = 2*jidx+1
        int jj = 2 * jidx + 1;
        int m = (jj <= 255) ? jj : (IMG - jj);
        float pm = (float)M_PI * (float)m;
        float fj = -1.0f / (pm * pm);
        int idx = (jj * k) & (IMG - 1);
        acc = fmaf(fj, cospif((float)idx * (1.0f / 256.0f)), acc);
    }
    #pragma unroll
    for (int o = 16; o; o >>= 1) acc += __shfl_xor_sync(0xffffffffu, acc, o);
    if (t == 0) {
        float ffk = 2.0f * (0.25f + acc);
        if (k > 0) {
            int m = (k <= 256) ? k : (IMG - k);          // |fftfreq|*N
            float x = (float)m * (1.0f / (float)IMG);    // exact
            ffk *= sinpif(x) / ((float)M_PI * x);        // sin(omega)/omega, even
        }
        g_ff[k] = ffk;
        if (k < NANG) {
            double th = (double)k * (M_PI / 179.0);      // linspace(0,180,180) deg
            g_trig[k] = make_float2((float)sin(th), (float)cos(th));
        }
    }
}

// ---------------- setup stage 2: one block per q ----------------
__global__ void setup_h() {                 // grid 512, block 128
    __shared__ float s_part[4];
    const int q = blockIdx.x;
    const int t = threadIdx.x;
    float acc = 0.0f;
    #pragma unroll
    for (int u = 0; u < 4; ++u) {
        int k = t * 4 + u;
        int idx = (k * q) & (IMG - 1);
        acc = fmaf(__ldg(&g_ff[k]), cospif((float)idx * (1.0f / 256.0f)), acc);
    }
    #pragma unroll
    for (int o = 16; o; o >>= 1) acc += __shfl_xor_sync(0xffffffffu, acc, o);
    if ((t & 31) == 0) s_part[t >> 5] = acc;
    __syncthreads();
    if (t == 0)
        g_h[q] = ((s_part[0] + s_part[1]) + (s_part[2] + s_part[3])) * (1.0f / (float)IMG);
}

// ---------------- filtering: circular conv + duplicated-pair fp16 rows ----------------
__global__ void filter_kernel(const float* __restrict__ sino) {
    __shared__ float s_row[2 * IMG];   // row duplicated -> no modulo
    __shared__ float s_hr[IMG];
    const int a = blockIdx.x;
    const int b = blockIdx.y;
    const int t = threadIdx.x;         // 0..127

    float4 r4 = reinterpret_cast<const float4*>(sino + (b * NANG + a) * IMG)[t];
    reinterpret_cast<float4*>(s_row)[t]       = r4;
    reinterpret_cast<float4*>(s_row)[t + 128] = r4;

    float4 h4 = reinterpret_cast<const float4*>(g_h)[t];   // h[4t..4t+3]
    s_hr[(IMG - (4 * t + 0)) & (IMG - 1)] = h4.x;
    s_hr[(IMG - (4 * t + 1)) & (IMG - 1)] = h4.y;
    s_hr[(IMG - (4 * t + 2)) & (IMG - 1)] = h4.z;
    s_hr[(IMG - (4 * t + 3)) & (IMG - 1)] = h4.w;

    // zero pads. Data samples live at 64..575. Slot s = (quad s, quad s+1):
    //   full-zero slots 0..62 and 576..703; low half of 63; high half of 575.
    if (b == 0) {
        if (t < 63) g_dup[a][t] = make_uint4(0u, 0u, 0u, 0u);
        if (t == 63) reinterpret_cast<uint2*>(&g_dup[a][63])[0] = make_uint2(0u, 0u);
    } else if (b == 1) {
        g_dup[a][576 + t] = make_uint4(0u, 0u, 0u, 0u);      // 576..703
        if (t == 0) reinterpret_cast<uint2*>(&g_dup[a][575])[1] = make_uint2(0u, 0u);
    }
    __syncthreads();

    float acc0 = 0.f, acc1 = 0.f, acc2 = 0.f, acc3 = 0.f;
    const int obase = 4 * t;
    float4 R0 = *reinterpret_cast<const float4*>(&s_row[obase]);
    #pragma unroll 4
    for (int u = 0; u < IMG; u += 4) {
        float4 HR = *reinterpret_cast<const float4*>(&s_hr[u]);                   // broadcast
        float4 R1 = *reinterpret_cast<const float4*>(&s_row[obase + u + 4]);      // sliding
        acc0 = fmaf(R0.x, HR.x, fmaf(R0.y, HR.y, fmaf(R0.z, HR.z, fmaf(R0.w, HR.w, acc0))));
        acc1 = fmaf(R0.y, HR.x, fmaf(R0.z, HR.y, fmaf(R0.w, HR.z, fmaf(R1.x, HR.w, acc1))));
        acc2 = fmaf(R0.z, HR.x, fmaf(R0.w, HR.y, fmaf(R1.x, HR.z, fmaf(R1.y, HR.w, acc2))));
        acc3 = fmaf(R0.w, HR.x, fmaf(R1.x, HR.y, fmaf(R1.y, HR.z, fmaf(R1.z, HR.w, acc3))));
        R0 = R1;
    }

    // duplicated-pair scatter: sample s -> low half of slot s, high half of slot s-1
    __half* dsth = reinterpret_cast<__half*>(&g_dup[a][0]);   // 8 halves per slot
    const int s0 = 64 + obase;
    float accs[4] = {acc0, acc1, acc2, acc3};
    #pragma unroll
    for (int i = 0; i < 4; ++i) {
        __half v = __float2half_rn(accs[i]);
        dsth[(s0 + i) * 8 + b]         = v;
        dsth[(s0 + i - 1) * 8 + 4 + b] = v;
    }
}

// ---------------- backprojection: 32x32 tile, grid.z=NZ, paired fp16 windows ---------------
// Per (block, angle): stage WSLOT=48 paired slots from base-2, base = floor(p_min_tile).
// One LDS.128 yields both bilinear taps (4 batches). il = floor(q) in [1, 47] always staged.
__global__ __launch_bounds__(512) void backproj_kernel() {
    __shared__ uint4  s_win[2][CH][WSLOT];  // 4.6 KB, double-buffered windows
    __shared__ float4 s_meta[2][CH];        // (sin, cos, offset, -)
    __shared__ float2 s_trig[HANG];

    const int t  = threadIdx.x;
    const int tx = t & 31;
    const int ty = t >> 5;             // 0..15
    const int w  = blockIdx.x * 32 + tx;
    const int y0 = blockIdx.y * 32 + ty;
    const int az0 = blockIdx.z * HANG;

    const float xf  = 255.0f - (float)w;
    const float yfa = (float)y0 - 256.0f;
    const float yfb = (float)(y0 + 16) - 256.0f;

    // block-level circle early-out (tile entirely outside radius 256)
    {
        float xhi = 255.0f - (float)(blockIdx.x * 32);
        float xlo = xhi - 31.0f;
        float ylo = (float)(blockIdx.y * 32) - 256.0f;
        float yhi = ylo + 31.0f;
        float mx = (xlo <= 0.0f && 0.0f <= xhi) ? 0.0f : fminf(fabsf(xlo), fabsf(xhi));
        float my = (ylo <= 0.0f && 0.0f <= yhi) ? 0.0f : fminf(fabsf(ylo), fabsf(yhi));
        if (fmaf(mx, mx, my * my) > 65536.0f) return;   // reduce kernel masks these pixels
    }

    if (t < HANG) s_trig[t] = g_trig[az0 + t];
    __syncthreads();                   // trig visible before staging

    const float xfmin = 224.0f - 32.0f * (float)blockIdx.x;
    const float yfmin = 32.0f * (float)blockIdx.y - 256.0f;
    const float yfmax = yfmin + 31.0f;

    const unsigned int sbase = (unsigned int)__cvta_generic_to_shared(&s_win[0][0][0]);

    const int st_ang = t / WSLOT;      // 0..2 for t < 144
    const int st_j   = t - st_ang * WSLOT;

    auto stage = [&](int c, int buf) {
        if (t < CH * WSLOT) {
            float2 sc = s_trig[c * CH + st_ang];
            float t0  = fmaf(xfmin, sc.x, 256.0f);
            float pmw = fminf(fmaf(yfmin, sc.y, t0), fmaf(yfmax, sc.y, t0));
            int base  = (int)floorf(pmw);
            const uint4* src = &g_dup[az0 + c * CH + st_ang][64 + base - 2 + st_j];
            unsigned int dst = sbase + (unsigned int)(((buf * CH + st_ang) * WSLOT + st_j) * 16);
            cp_async16(dst, src);
            if (st_j == 0)
                s_meta[buf][st_ang] = make_float4(sc.x, sc.y, 258.0f - (float)base, 0.f);
            cp_async_commit();
        }
    };

    stage(0, 0);

    float2 ac0A = {0.f, 0.f}, ac0B = {0.f, 0.f};   // pixel a (y0): batches 01, 23
    float2 ac1A = {0.f, 0.f}, ac1B = {0.f, 0.f};   // pixel b (y0+16)

    for (int c = 0; c < NCZ; ++c) {
        if (c + 1 < NCZ) { stage(c + 1, (c + 1) & 1); cp_async_wait<1>(); }
        else             { cp_async_wait<0>(); }
        __syncthreads();

        #pragma unroll
        for (int ci = 0; ci < CH; ++ci) {
            const float4 m  = s_meta[c & 1][ci];        // sin, cos, offset
            const float  pq = fmaf(xf, m.x, m.z);
            const uint4* win = s_win[c & 1][ci];

            // pixel a
            {
                float q   = fmaf(yfa, m.y, pq);
                float fl  = floorf(q);
                float fr  = q - fl;
                int   il  = (int)fl;
                __half2 fr2 = __float2half2_rn(fr);
                uint4 u = win[il];                      // (v0a v0b | v1a v1b)
                __half2 v0a = *reinterpret_cast<__half2*>(&u.x);
                __half2 v0b = *reinterpret_cast<__half2*>(&u.y);
                __half2 v1a = *reinterpret_cast<__half2*>(&u.z);
                __half2 v1b = *reinterpret_cast<__half2*>(&u.w);
                __half2 la = __hfma2(fr2, __hsub2(v1a, v0a), v0a);
                __half2 lb = __hfma2(fr2, __hsub2(v1b, v0b), v0b);
                addf32x2(ac0A, __half22float2(la));
                addf32x2(ac0B, __half22float2(lb));
            }
            // pixel b
            {
                float q   = fmaf(yfb, m.y, pq);
                float fl  = floorf(q);
                float fr  = q - fl;
                int   il  = (int)fl;
                __half2 fr2 = __float2half2_rn(fr);
                uint4 u = win[il];
                __half2 v0a = *reinterpret_cast<__half2*>(&u.x);
                __half2 v0b = *reinterpret_cast<__half2*>(&u.y);
                __half2 v1a = *reinterpret_cast<__half2*>(&u.z);
                __half2 v1b = *reinterpret_cast<__half2*>(&u.w);
                __half2 la = __hfma2(fr2, __hsub2(v1a, v0a), v0a);
                __half2 lb = __hfma2(fr2, __hsub2(v1b, v0b), v0b);
                addf32x2(ac1A, __half22float2(la));
                addf32x2(ac1B, __half22float2(lb));
            }
        }
        __syncthreads();               // protect windows/meta before next overwrite
    }

    g_part[blockIdx.z][y0 * IMG + w]        = make_float4(ac0A.x, ac0A.y, ac0B.x, ac0B.y);
    g_part[blockIdx.z][(y0 + 16) * IMG + w] = make_float4(ac1A.x, ac1A.y, ac1B.x, ac1B.y);
}

// ---------------- reduce: add slices, apply circle mask + pi/(2A), planar output ----------
__global__ __launch_bounds__(512) void reduce_kernel(float* __restrict__ out) {
    const int pix = blockIdx.x * 512 + threadIdx.x;
    const float4 p0 = g_part[0][pix];
    const float4 p1 = g_part[1][pix];
    const float4 p2 = g_part[2][pix];
    const float4 p3 = g_part[3][pix];
    const int x = pix & (IMG - 1);
    const int y = pix >> 9;
    const float xf = 255.0f - (float)x;
    const float yf = (float)y - 256.0f;
    const float g = (fmaf(xf, xf, yf * yf) <= 65536.0f) ? (float)(M_PI / (2.0 * NANG)) : 0.0f;
    out[0 * IMG * IMG + pix] = ((p0.x + p1.x) + (p2.x + p3.x)) * g;
    out[1 * IMG * IMG + pix] = ((p0.y + p1.y) + (p2.y + p3.y)) * g;
    out[2 * IMG * IMG + pix] = ((p0.z + p1.z) + (p2.z + p3.z)) * g;
    out[3 * IMG * IMG + pix] = ((p0.w + p1.w) + (p2.w + p3.w)) * g;
}

// ---------------- launcher ----------------
extern "C" void kernel_launch(void* const* d_in, const int* in_sizes, int n_in,
                              void* d_out, int out_size) {
    const float* sino = (const float*)d_in[0];
    float* out = (float*)d_out;

    setup_ff<<<512, 32>>>();
    setup_h<<<512, 128>>>();
    filter_kernel<<<dim3(NANG, NBAT), 128>>>(sino);
    backproj_kernel<<<dim3(IMG / 32, IMG / 32, NZ), 512>>>();
    reduce_kernel<<<IMG * IMG / 512, 512>>>(out);
}